// round 12
// baseline (speedup 1.0000x reference)
#include <cuda_runtime.h>
#include <math.h>
#include <stdint.h>

#define B_ 4
#define T_ 1024
#define D_ 512
#define H_ 8
#define DH_ 64
#define TE_ 2048
#define NTOK (B_*T_)

// ---------------- scratch ----------------
__device__ float g_xn[NTOK * D_];
__device__ float g_q [NTOK * D_];
__device__ float g_k [NTOK * D_];
__device__ float g_v [NTOK * D_];
__device__ float g_y [NTOK * D_];
__device__ float g_h [NTOK * D_];
__device__ float g_embout[B_ * 2 * D_];
__device__ float g_embpart[8 * B_ * 2 * D_];
__device__ float g_sbuf[(size_t)B_ * H_ * T_ * T_];   // scores [b,h,n,m]

// ---------------- helpers ----------------
__device__ __forceinline__ uint32_t f2tf32(float x) {
    uint32_t u;
    asm("cvt.rna.tf32.f32 %0, %1;" : "=r"(u) : "f"(x));
    return u;
}

__device__ __forceinline__ void mma_tf32(float d[4], const uint32_t a[4], const uint32_t b[2]) {
    asm volatile(
        "mma.sync.aligned.m16n8k8.row.col.f32.tf32.tf32.f32 "
        "{%0,%1,%2,%3}, {%4,%5,%6,%7}, {%8,%9}, {%0,%1,%2,%3};\n"
        : "+f"(d[0]), "+f"(d[1]), "+f"(d[2]), "+f"(d[3])
        : "r"(a[0]), "r"(a[1]), "r"(a[2]), "r"(a[3]), "r"(b[0]), "r"(b[1]));
}

// ---------------- layernorm ----------------
__global__ void ln_kernel(const float* __restrict__ x,
                          const float* __restrict__ g,
                          const float* __restrict__ b,
                          float* __restrict__ out) {
    int row = blockIdx.x;
    const float* xr = x + (size_t)row * D_;
    int tid = threadIdx.x;
    float v0 = xr[tid], v1 = xr[tid + 256];
    float s = v0 + v1, sq = v0*v0 + v1*v1;
    __shared__ float sh_s[8], sh_q[8];
    for (int o = 16; o > 0; o >>= 1) {
        s  += __shfl_xor_sync(0xffffffff, s,  o);
        sq += __shfl_xor_sync(0xffffffff, sq, o);
    }
    int warp = tid >> 5, lane = tid & 31;
    if (lane == 0) { sh_s[warp] = s; sh_q[warp] = sq; }
    __syncthreads();
    if (warp == 0) {
        s  = (lane < 8) ? sh_s[lane] : 0.f;
        sq = (lane < 8) ? sh_q[lane] : 0.f;
        for (int o = 4; o > 0; o >>= 1) {
            s  += __shfl_xor_sync(0xffffffff, s,  o);
            sq += __shfl_xor_sync(0xffffffff, sq, o);
        }
        if (lane == 0) { sh_s[0] = s; sh_q[0] = sq; }
    }
    __syncthreads();
    float mean = sh_s[0] * (1.f / D_);
    float var  = sh_q[0] * (1.f / D_) - mean * mean;
    float rs = rsqrtf(var + 1e-5f);
    float* orow = out + (size_t)row * D_;
    orow[tid]       = (v0 - mean) * rs * g[tid]       + b[tid];
    orow[tid + 256] = (v1 - mean) * rs * g[tid + 256] + b[tid + 256];
}

// ---------------- tf32 SGEMM 128x128, double-buffered ----------------
__global__ __launch_bounds__(256, 2)
void sgemm_tf32_128(const float* __restrict__ A,
                    const float* __restrict__ W0, const float* __restrict__ W1,
                    const float* __restrict__ W2,
                    const float* __restrict__ Bi0, const float* __restrict__ Bi1,
                    const float* __restrict__ Bi2,
                    float* __restrict__ C0, float* __restrict__ C1,
                    float* __restrict__ C2,
                    const float* __restrict__ resid,
                    int M, int N, int K) {
    __shared__ uint32_t As[2][128][36];
    __shared__ uint32_t Bs[2][32][136];
    int z = blockIdx.z;
    const float* W    = (z == 0) ? W0  : (z == 1) ? W1  : W2;
    const float* bias = (z == 0) ? Bi0 : (z == 1) ? Bi1 : Bi2;
    float*       C    = (z == 0) ? C0  : (z == 1) ? C1  : C2;

    int bm = blockIdx.y * 128, bn = blockIdx.x * 128;
    int tid = threadIdx.x;
    int warp = tid >> 5, lane = tid & 31;
    int gid = lane >> 2, tig = lane & 3;
    int wm = warp >> 2, wn = warp & 3;

    int ar = tid >> 3, ac4 = (tid & 7) * 4;
    int br = tid >> 5, bc4 = (tid & 31) * 4;

    float4 ra[4], rb[4];
    float d[4][4][4] = {};
    const int nch = K / 32;

    #pragma unroll
    for (int p = 0; p < 4; p++)
        ra[p] = *(const float4*)&A[(size_t)(bm + ar + 32*p) * K + ac4];
    #pragma unroll
    for (int p = 0; p < 4; p++)
        rb[p] = *(const float4*)&W[(size_t)(br + 8*p) * N + bn + bc4];
    #pragma unroll
    for (int p = 0; p < 4; p++) {
        As[0][ar + 32*p][ac4+0] = f2tf32(ra[p].x); As[0][ar + 32*p][ac4+1] = f2tf32(ra[p].y);
        As[0][ar + 32*p][ac4+2] = f2tf32(ra[p].z); As[0][ar + 32*p][ac4+3] = f2tf32(ra[p].w);
    }
    #pragma unroll
    for (int p = 0; p < 4; p++) {
        Bs[0][br + 8*p][bc4+0] = f2tf32(rb[p].x); Bs[0][br + 8*p][bc4+1] = f2tf32(rb[p].y);
        Bs[0][br + 8*p][bc4+2] = f2tf32(rb[p].z); Bs[0][br + 8*p][bc4+3] = f2tf32(rb[p].w);
    }

    for (int i = 0; i < nch; i++) {
        __syncthreads();
        int cur = i & 1;
        if (i + 1 < nch) {
            int k0 = (i + 1) * 32;
            #pragma unroll
            for (int p = 0; p < 4; p++)
                ra[p] = *(const float4*)&A[(size_t)(bm + ar + 32*p) * K + k0 + ac4];
            #pragma unroll
            for (int p = 0; p < 4; p++)
                rb[p] = *(const float4*)&W[(size_t)(k0 + br + 8*p) * N + bn + bc4];
        }
        #pragma unroll
        for (int ks = 0; ks < 4; ks++) {
            int k = ks * 8;
            uint32_t a[4][4];
            #pragma unroll
            for (int mi = 0; mi < 4; mi++) {
                int m = wm * 64 + mi * 16 + gid;
                a[mi][0] = As[cur][m][k + tig];
                a[mi][1] = As[cur][m + 8][k + tig];
                a[mi][2] = As[cur][m][k + tig + 4];
                a[mi][3] = As[cur][m + 8][k + tig + 4];
            }
            #pragma unroll
            for (int ni = 0; ni < 4; ni++) {
                int n = wn * 32 + ni * 8 + gid;
                uint32_t b[2];
                b[0] = Bs[cur][k + tig][n];
                b[1] = Bs[cur][k + tig + 4][n];
                #pragma unroll
                for (int mi = 0; mi < 4; mi++)
                    mma_tf32(d[mi][ni], a[mi], b);
            }
        }
        if (i + 1 < nch) {
            int nxt = cur ^ 1;
            #pragma unroll
            for (int p = 0; p < 4; p++) {
                As[nxt][ar + 32*p][ac4+0] = f2tf32(ra[p].x); As[nxt][ar + 32*p][ac4+1] = f2tf32(ra[p].y);
                As[nxt][ar + 32*p][ac4+2] = f2tf32(ra[p].z); As[nxt][ar + 32*p][ac4+3] = f2tf32(ra[p].w);
            }
            #pragma unroll
            for (int p = 0; p < 4; p++) {
                Bs[nxt][br + 8*p][bc4+0] = f2tf32(rb[p].x); Bs[nxt][br + 8*p][bc4+1] = f2tf32(rb[p].y);
                Bs[nxt][br + 8*p][bc4+2] = f2tf32(rb[p].z); Bs[nxt][br + 8*p][bc4+3] = f2tf32(rb[p].w);
            }
        }
    }

    #pragma unroll
    for (int mi = 0; mi < 4; mi++) {
        int r0 = bm + wm * 64 + mi * 16 + gid;
        int r1 = r0 + 8;
        #pragma unroll
        for (int ni = 0; ni < 4; ni++) {
            int c = bn + wn * 32 + ni * 8 + tig * 2;
            float b0 = bias[c], b1 = bias[c + 1];
            float v00 = d[mi][ni][0] + b0, v01 = d[mi][ni][1] + b1;
            float v10 = d[mi][ni][2] + b0, v11 = d[mi][ni][3] + b1;
            if (resid) {
                const float2 rA = *(const float2*)&resid[(size_t)r0 * N + c];
                const float2 rB = *(const float2*)&resid[(size_t)r1 * N + c];
                v00 += rA.x; v01 += rA.y; v10 += rB.x; v11 += rB.y;
            }
            *(float2*)&C[(size_t)r0 * N + c] = make_float2(v00, v01);
            *(float2*)&C[(size_t)r1 * N + c] = make_float2(v10, v11);
        }
    }
}

// ---------------- fused attention, tf32 MMA ----------------
// 16-row tile, 64-key chunks, 256 threads, 2 blocks/SM for latency overlap.
#define QROWS 16
#define MCHUNK 64
#define NCHUNK (T_/MCHUNK)
#define QPITCH 76
#define PF_STRIDE 33
#define PF_FLOATS (128*PF_STRIDE*4)          // 16896
#define SROW(r) ((r)*1028)
#define ATTN_SMEM_FLOATS (PF_FLOATS + QROWS*QPITCH + 2*MCHUNK*QPITCH)  // 27840
#define ATTN_SMEM_BYTES (ATTN_SMEM_FLOATS*4) // 111360
#define ATHR 256

__device__ __forceinline__ void fill_kv(uint32_t* __restrict__ dst,
                                        const float* __restrict__ src,
                                        int b, int base, int h, int tid) {
    #pragma unroll
    for (int p = 0; p < 4; p++) {
        int i = tid + p * ATHR;
        int r = i >> 4, c4 = (i & 15) * 4;
        float4 v = *(const float4*)&src[(size_t)(b * T_ + base + r) * D_ + h * DH_ + c4];
        uint4 u;
        u.x = f2tf32(v.x); u.y = f2tf32(v.y); u.z = f2tf32(v.z); u.w = f2tf32(v.w);
        *(uint4*)&dst[r*QPITCH + c4] = u;
    }
}

__global__ __launch_bounds__(ATHR, 2)
void attn_kernel(const float* __restrict__ qb,
                 const float* __restrict__ kb,
                 const float* __restrict__ vb,
                 const float* __restrict__ mask,
                 float* __restrict__ sbuf,
                 float* __restrict__ yb) {
    extern __shared__ float sm[];
    float*    P   = sm;                              // S rows (16x1028) alias Pf
    uint32_t* Qs  = (uint32_t*)(sm + PF_FLOATS);     // [16][76]
    uint32_t* KV0 = Qs + QROWS * QPITCH;             // [64][76]
    uint32_t* KV1 = KV0 + MCHUNK * QPITCH;
    float* rowinv = (float*)Qs;                      // alias after frag hoist

    int h = blockIdx.y, b = blockIdx.z;
    int n0 = blockIdx.x * QROWS;
    int tid = threadIdx.x;
    int warp = tid >> 5, lane = tid & 31;
    int gid = lane >> 2, tig = lane & 3;
    const float invs = 0.125f;

    // stage Q tile 16x64 -> smem (packed STS.128)
    {
        int r = tid >> 4, c4 = (tid & 15) * 4;
        float4 v = *(const float4*)&qb[(size_t)(b * T_ + n0 + r) * D_ + h * DH_ + c4];
        uint4 u;
        u.x = f2tf32(v.x); u.y = f2tf32(v.y); u.z = f2tf32(v.z); u.w = f2tf32(v.w);
        *(uint4*)&Qs[r*QPITCH + c4] = u;
    }
    fill_kv(KV0, kb, b, 0, h, tid);
    __syncthreads();

    // hoist Q fragments (rows gid / gid+8)
    uint32_t qf[8][4];
    #pragma unroll
    for (int ks = 0; ks < 8; ks++) {
        qf[ks][0] = Qs[gid*QPITCH + ks*8 + tig];
        qf[ks][1] = Qs[(gid+8)*QPITCH + ks*8 + tig];
        qf[ks][2] = Qs[gid*QPITCH + ks*8 + tig + 4];
        qf[ks][3] = Qs[(gid+8)*QPITCH + ks*8 + tig + 4];
    }

    // per-warp row bases
    int r0 = gid, r1 = gid + 8;
    const float* mrow0 = mask + (size_t)(b * T_ + n0 + r0) * T_;
    const float* mrow1 = mask + (size_t)(b * T_ + n0 + r1) * T_;
    float* sb0 = sbuf + ((((size_t)b * H_ + h) * T_ + n0 + r0) * T_);
    float* sb1 = sbuf + ((((size_t)b * H_ + h) * T_ + n0 + r1) * T_);
    float* s0 = P + SROW(r0);
    float* s1 = P + SROW(r1);

    // ---- QK^T ---- 8 warps, warp tile 16x8, double-buffered K
    #pragma unroll 1
    for (int ci = 0; ci < NCHUNK; ci++) {
        if (ci) __syncthreads();
        uint32_t* cur = (ci & 1) ? KV1 : KV0;
        int mc = ci * MCHUNK;
        int mbase = mc + warp * 8 + tig * 2;
        float2 mk0 = *(const float2*)&mrow0[mbase];
        float2 mk1 = *(const float2*)&mrow1[mbase];
        if (ci + 1 < NCHUNK)
            fill_kv((ci & 1) ? KV0 : KV1, kb, b, (ci + 1) * MCHUNK, h, tid);

        float d[4] = {};
        #pragma unroll
        for (int ks = 0; ks < 8; ks++) {
            int k = ks * 8;
            int n = warp * 8 + gid;
            uint32_t bb[2];
            bb[0] = cur[n*QPITCH + k + tig];
            bb[1] = cur[n*QPITCH + k + tig + 4];
            mma_tf32(d, qf[ks], bb);
        }
        float v00 = d[0] * invs * mk0.x, v01 = d[1] * invs * mk0.y;
        float v10 = d[2] * invs * mk1.x, v11 = d[3] * invs * mk1.y;
        *(float2*)&s0[mbase] = make_float2(v00, v01);
        *(float2*)&s1[mbase] = make_float2(v10, v11);
        *(float2*)&sb0[mbase] = make_float2(v00, v01);
        *(float2*)&sb1[mbase] = make_float2(v10, v11);
        __syncthreads();
    }
    fill_kv(KV0, vb, b, 0, h, tid);
    __syncthreads();

    // ---- softmax: one row pair per warp; STS.64 quad halves to Pf ----
    {
        int pp = warp;                 // rows pp, pp+8
        const float* rlo = P + SROW(pp);
        const float* rhi = P + SROW(pp + 8);
        float2 buf[32];
        float suml = 0.f, sumh = 0.f;
        #pragma unroll
        for (int it = 0; it < 8; it++) {
            int c = it * 128 + lane * 4;
            float4 lo = *(const float4*)&rlo[c];
            float4 hi = *(const float4*)&rhi[c];
            float el0 = __expf(lo.x), el1 = __expf(lo.y), el2 = __expf(lo.z), el3 = __expf(lo.w);
            float eh0 = __expf(hi.x), eh1 = __expf(hi.y), eh2 = __expf(hi.z), eh3 = __expf(hi.w);
            suml += (el0 + el1) + (el2 + el3);
            sumh += (eh0 + eh1) + (eh2 + eh3);
            buf[it*4+0] = make_float2(__uint_as_float(f2tf32(el0)), __uint_as_float(f2tf32(eh0)));
            buf[it*4+1] = make_float2(__uint_as_float(f2tf32(el1)), __uint_as_float(f2tf32(eh1)));
            buf[it*4+2] = make_float2(__uint_as_float(f2tf32(el2)), __uint_as_float(f2tf32(eh2)));
            buf[it*4+3] = make_float2(__uint_as_float(f2tf32(el3)), __uint_as_float(f2tf32(eh3)));
        }
        #pragma unroll
        for (int o = 16; o > 0; o >>= 1) {
            suml += __shfl_xor_sync(0xffffffff, suml, o);
            sumh += __shfl_xor_sync(0xffffffff, sumh, o);
        }
        if (lane == 0) {
            rowinv[pp]     = 1.f / suml;
            rowinv[pp + 8] = 1.f / sumh;
        }
        __syncthreads();               // all S reads done before Pf writes
        int eoff = (lane & 1) * 2;
        #pragma unroll
        for (int it = 0; it < 8; it++) {
            int g = it * 16 + (lane >> 1);
            float* qb_ = P + (g * PF_STRIDE + pp * 4) * 4 + eoff;
            *(float2*)&qb_[0]  = buf[it*4+0];
            *(float2*)&qb_[4]  = buf[it*4+1];
            *(float2*)&qb_[8]  = buf[it*4+2];
            *(float2*)&qb_[12] = buf[it*4+3];
        }
    }
    __syncthreads();                   // Pf + rowinv + V chunk 0 visible

    // ---- PV ---- 8 warps, warp tile 16x8; A via single LDS.128 from Pf
    float dy[4] = {};
    #pragma unroll 1
    for (int ci = 0; ci < NCHUNK; ci++) {
        uint32_t* cur = (ci & 1) ? KV1 : KV0;
        if (ci + 1 < NCHUNK)
            fill_kv((ci & 1) ? KV0 : KV1, vb, b, (ci + 1) * MCHUNK, h, tid);
        #pragma unroll 4
        for (int ks = 0; ks < 8; ks++) {
            int g = ci * 8 + ks;
            float4 aq = *(const float4*)&P[(g * PF_STRIDE + lane) * 4];
            uint32_t a[4];
            a[0] = __float_as_uint(aq.x); a[1] = __float_as_uint(aq.y);
            a[2] = __float_as_uint(aq.z); a[3] = __float_as_uint(aq.w);
            int k = ks * 8;
            int n = warp * 8 + gid;
            uint32_t bb[2];
            bb[0] = cur[(k + tig)*QPITCH + n];
            bb[1] = cur[(k + tig + 4)*QPITCH + n];
            mma_tf32(dy, a, bb);
        }
        __syncthreads();
    }
    {
        float inv0 = rowinv[gid], inv1 = rowinv[gid + 8];
        int rr0 = n0 + gid, rr1 = n0 + gid + 8;
        int c = h * DH_ + warp * 8 + tig * 2;
        *(float2*)&yb[(size_t)(b * T_ + rr0) * D_ + c] = make_float2(dy[0]*inv0, dy[1]*inv0);
        *(float2*)&yb[(size_t)(b * T_ + rr1) * D_ + c] = make_float2(dy[2]*inv1, dy[3]*inv1);
    }
}

// ---------------- transpose [b,h,n,m] -> [b,n,m,h] ----------------
__global__ void transpose_attn(const float* __restrict__ sbuf,
                               float* __restrict__ attn) {
    int n = blockIdx.x * 2 + (threadIdx.x >> 8);
    int b = blockIdx.y;
    int m4 = (threadIdx.x & 255) * 4;
    float v[8][4];
    #pragma unroll
    for (int h = 0; h < H_; h++) {
        float4 t = __ldg((const float4*)&sbuf[((((size_t)b * H_ + h) * T_ + n) * T_) + m4]);
        v[h][0] = t.x; v[h][1] = t.y; v[h][2] = t.z; v[h][3] = t.w;
    }
    float* obase = attn + (((size_t)(b * T_ + n) * T_ + m4)) * H_;
    #pragma unroll
    for (int j = 0; j < 4; j++) {
        float4* o = (float4*)(obase + j * H_);
        o[0] = make_float4(v[0][j], v[1][j], v[2][j], v[3][j]);
        o[1] = make_float4(v[4][j], v[5][j], v[6][j], v[7][j]);
    }
}

// ---------------- emb path: partial GEMV over t-chunks ----------------
__global__ void emb_partial(const float* __restrict__ emb,
                            const float* __restrict__ w,
                            float* __restrict__ part) {
    int c = blockIdx.x, b = blockIdx.y;
    int j = threadIdx.x;
    __shared__ float se[256];
    if (j < 256) {
        float e = emb[(size_t)b * TE_ + c * 256 + j];
        se[j] = __fdividef(e, 1.f + __expf(-e));
    }
    __syncthreads();
    float acc = 0.f;
    const float* wb = w + (size_t)(c * 256) * (2 * D_) + j;
    #pragma unroll 8
    for (int t = 0; t < 256; t++)
        acc += se[t] * wb[(size_t)t * (2 * D_)];
    part[((size_t)(b * 8 + c)) * (2 * D_) + j] = acc;
}

__global__ void emb_reduce(const float* __restrict__ part,
                           const float* __restrict__ bias,
                           float* __restrict__ out) {
    int b = blockIdx.x, j = threadIdx.x;
    float acc = bias[j];
    #pragma unroll
    for (int c = 0; c < 8; c++)
        acc += part[((size_t)(b * 8 + c)) * (2 * D_) + j];
    out[(size_t)b * (2 * D_) + j] = acc;
}

// ---------------- stylization ----------------
__global__ void styl_kernel(const float* __restrict__ y,
                            const float* __restrict__ g,
                            const float* __restrict__ bta,
                            const float* __restrict__ embout,
                            float* __restrict__ out) {
    int row = blockIdx.x;
    int b = row / T_;
    const float* yr = y + (size_t)row * D_;
    int tid = threadIdx.x;
    float v0 = yr[tid], v1 = yr[tid + 256];
    float s = v0 + v1, sq = v0*v0 + v1*v1;
    __shared__ float sh_s[8], sh_q[8];
    for (int o = 16; o > 0; o >>= 1) {
        s  += __shfl_xor_sync(0xffffffff, s,  o);
        sq += __shfl_xor_sync(0xffffffff, sq, o);
    }
    int warp = tid >> 5, lane = tid & 31;
    if (lane == 0) { sh_s[warp] = s; sh_q[warp] = sq; }
    __syncthreads();
    if (warp == 0) {
        s  = (lane < 8) ? sh_s[lane] : 0.f;
        sq = (lane < 8) ? sh_q[lane] : 0.f;
        for (int o = 4; o > 0; o >>= 1) {
            s  += __shfl_xor_sync(0xffffffff, s,  o);
            sq += __shfl_xor_sync(0xffffffff, sq, o);
        }
        if (lane == 0) { sh_s[0] = s; sh_q[0] = sq; }
    }
    __syncthreads();
    float mean = sh_s[0] * (1.f / D_);
    float var  = sh_q[0] * (1.f / D_) - mean * mean;
    float rs = rsqrtf(var + 1e-5f);
    const float* eo = embout + (size_t)b * (2 * D_);
    float* orow = out + (size_t)row * D_;
    {
        int c = tid;
        float ln = (v0 - mean) * rs * g[c] + bta[c];
        float hh = ln * (1.f + eo[c]) + eo[D_ + c];
        orow[c] = __fdividef(hh, 1.f + __expf(-hh));
    }
    {
        int c = tid + 256;
        float ln = (v1 - mean) * rs * g[c] + bta[c];
        float hh = ln * (1.f + eo[c]) + eo[D_ + c];
        orow[c] = __fdividef(hh, 1.f + __expf(-hh));
    }
}

// ---------------- launch ----------------
extern "C" void kernel_launch(void* const* d_in, const int* in_sizes, int n_in,
                              void* d_out, int out_size) {
    const float* x      = (const float*)d_in[0];
    const float* emb    = (const float*)d_in[1];
    const float* mask   = (const float*)d_in[2];
    const float* ln_g   = (const float*)d_in[3];
    const float* ln_b   = (const float*)d_in[4];
    const float* wq     = (const float*)d_in[5];
    const float* bq     = (const float*)d_in[6];
    const float* wk     = (const float*)d_in[7];
    const float* bk     = (const float*)d_in[8];
    const float* wv     = (const float*)d_in[9];
    const float* bv     = (const float*)d_in[10];
    const float* sb_g   = (const float*)d_in[11];
    const float* sb_b   = (const float*)d_in[12];
    const float* emb_w  = (const float*)d_in[13];
    const float* emb_b  = (const float*)d_in[14];
    const float* out_w  = (const float*)d_in[15];
    const float* out_b  = (const float*)d_in[16];

    float* out0 = (float*)d_out;                       // x + h : [4,1024,512]
    float* attn = out0 + (size_t)NTOK * D_;            // attention : [4,1024,1024,8]

    float *xn, *q, *k, *v, *y, *hb, *eo, *ep, *sb;
    cudaGetSymbolAddress((void**)&xn, g_xn);
    cudaGetSymbolAddress((void**)&q,  g_q);
    cudaGetSymbolAddress((void**)&k,  g_k);
    cudaGetSymbolAddress((void**)&v,  g_v);
    cudaGetSymbolAddress((void**)&y,  g_y);
    cudaGetSymbolAddress((void**)&hb, g_h);
    cudaGetSymbolAddress((void**)&eo, g_embout);
    cudaGetSymbolAddress((void**)&ep, g_embpart);
    cudaGetSymbolAddress((void**)&sb, g_sbuf);

    cudaFuncSetAttribute(attn_kernel, cudaFuncAttributeMaxDynamicSharedMemorySize,
                         ATTN_SMEM_BYTES);

    ln_kernel<<<NTOK, 256>>>(x, ln_g, ln_b, xn);

    dim3 gq(D_ / 128, NTOK / 128, 3);
    sgemm_tf32_128<<<gq, 256>>>(xn, wq, wk, wv, bq, bk, bv, q, k, v,
                                nullptr, NTOK, D_, D_);

    attn_kernel<<<dim3(T_ / QROWS, H_, B_), ATHR, ATTN_SMEM_BYTES>>>(q, k, v, mask, sb, y);

    transpose_attn<<<dim3(T_ / 2, B_), 512>>>(sb, attn);

    emb_partial<<<dim3(8, B_), 1024>>>(emb, emb_w, ep);
    emb_reduce<<<B_, 1024>>>(ep, emb_b, eo);
    styl_kernel<<<NTOK, 256>>>(y, sb_g, sb_b, eo, hb);

    dim3 go(D_ / 128, NTOK / 128, 1);
    sgemm_tf32_128<<<go, 256>>>(hb, out_w, out_w, out_w, out_b, out_b, out_b,
                                out0, out0, out0, x, NTOK, D_, D_);
}

// round 13
// speedup vs baseline: 1.0572x; 1.0572x over previous
#include <cuda_runtime.h>
#include <math.h>
#include <stdint.h>

#define B_ 4
#define T_ 1024
#define D_ 512
#define H_ 8
#define DH_ 64
#define TE_ 2048
#define NTOK (B_*T_)

// ---------------- scratch ----------------
__device__ float g_xn[NTOK * D_];
__device__ float g_q [NTOK * D_];
__device__ float g_k [NTOK * D_];
__device__ float g_v [NTOK * D_];
__device__ float g_y [NTOK * D_];
__device__ float g_h [NTOK * D_];
__device__ float g_embout[B_ * 2 * D_];
__device__ float g_embpart[8 * B_ * 2 * D_];
__device__ float g_sbuf[(size_t)B_ * H_ * T_ * T_];   // scores [b,h,n,m]

// ---------------- helpers ----------------
__device__ __forceinline__ uint32_t f2tf32(float x) {
    uint32_t u;
    asm("cvt.rna.tf32.f32 %0, %1;" : "=r"(u) : "f"(x));
    return u;
}

__device__ __forceinline__ void mma_tf32(float d[4], const uint32_t a[4], const uint32_t b[2]) {
    asm volatile(
        "mma.sync.aligned.m16n8k8.row.col.f32.tf32.tf32.f32 "
        "{%0,%1,%2,%3}, {%4,%5,%6,%7}, {%8,%9}, {%0,%1,%2,%3};\n"
        : "+f"(d[0]), "+f"(d[1]), "+f"(d[2]), "+f"(d[3])
        : "r"(a[0]), "r"(a[1]), "r"(a[2]), "r"(a[3]), "r"(b[0]), "r"(b[1]));
}

// ---------------- layernorm ----------------
__global__ void ln_kernel(const float* __restrict__ x,
                          const float* __restrict__ g,
                          const float* __restrict__ b,
                          float* __restrict__ out) {
    int row = blockIdx.x;
    const float* xr = x + (size_t)row * D_;
    int tid = threadIdx.x;
    float v0 = xr[tid], v1 = xr[tid + 256];
    float s = v0 + v1, sq = v0*v0 + v1*v1;
    __shared__ float sh_s[8], sh_q[8];
    for (int o = 16; o > 0; o >>= 1) {
        s  += __shfl_xor_sync(0xffffffff, s,  o);
        sq += __shfl_xor_sync(0xffffffff, sq, o);
    }
    int warp = tid >> 5, lane = tid & 31;
    if (lane == 0) { sh_s[warp] = s; sh_q[warp] = sq; }
    __syncthreads();
    if (warp == 0) {
        s  = (lane < 8) ? sh_s[lane] : 0.f;
        sq = (lane < 8) ? sh_q[lane] : 0.f;
        for (int o = 4; o > 0; o >>= 1) {
            s  += __shfl_xor_sync(0xffffffff, s,  o);
            sq += __shfl_xor_sync(0xffffffff, sq, o);
        }
        if (lane == 0) { sh_s[0] = s; sh_q[0] = sq; }
    }
    __syncthreads();
    float mean = sh_s[0] * (1.f / D_);
    float var  = sh_q[0] * (1.f / D_) - mean * mean;
    float rs = rsqrtf(var + 1e-5f);
    float* orow = out + (size_t)row * D_;
    orow[tid]       = (v0 - mean) * rs * g[tid]       + b[tid];
    orow[tid + 256] = (v1 - mean) * rs * g[tid + 256] + b[tid + 256];
}

// ---------------- tf32 SGEMM 128x128, double-buffered ----------------
__global__ __launch_bounds__(256, 2)
void sgemm_tf32_128(const float* __restrict__ A,
                    const float* __restrict__ W0, const float* __restrict__ W1,
                    const float* __restrict__ W2,
                    const float* __restrict__ Bi0, const float* __restrict__ Bi1,
                    const float* __restrict__ Bi2,
                    float* __restrict__ C0, float* __restrict__ C1,
                    float* __restrict__ C2,
                    const float* __restrict__ resid,
                    int M, int N, int K) {
    __shared__ uint32_t As[2][128][36];
    __shared__ uint32_t Bs[2][32][136];
    int z = blockIdx.z;
    const float* W    = (z == 0) ? W0  : (z == 1) ? W1  : W2;
    const float* bias = (z == 0) ? Bi0 : (z == 1) ? Bi1 : Bi2;
    float*       C    = (z == 0) ? C0  : (z == 1) ? C1  : C2;

    int bm = blockIdx.y * 128, bn = blockIdx.x * 128;
    int tid = threadIdx.x;
    int warp = tid >> 5, lane = tid & 31;
    int gid = lane >> 2, tig = lane & 3;
    int wm = warp >> 2, wn = warp & 3;

    int ar = tid >> 3, ac4 = (tid & 7) * 4;
    int br = tid >> 5, bc4 = (tid & 31) * 4;

    float4 ra[4], rb[4];
    float d[4][4][4] = {};
    const int nch = K / 32;

    #pragma unroll
    for (int p = 0; p < 4; p++)
        ra[p] = *(const float4*)&A[(size_t)(bm + ar + 32*p) * K + ac4];
    #pragma unroll
    for (int p = 0; p < 4; p++)
        rb[p] = *(const float4*)&W[(size_t)(br + 8*p) * N + bn + bc4];
    #pragma unroll
    for (int p = 0; p < 4; p++) {
        As[0][ar + 32*p][ac4+0] = f2tf32(ra[p].x); As[0][ar + 32*p][ac4+1] = f2tf32(ra[p].y);
        As[0][ar + 32*p][ac4+2] = f2tf32(ra[p].z); As[0][ar + 32*p][ac4+3] = f2tf32(ra[p].w);
    }
    #pragma unroll
    for (int p = 0; p < 4; p++) {
        Bs[0][br + 8*p][bc4+0] = f2tf32(rb[p].x); Bs[0][br + 8*p][bc4+1] = f2tf32(rb[p].y);
        Bs[0][br + 8*p][bc4+2] = f2tf32(rb[p].z); Bs[0][br + 8*p][bc4+3] = f2tf32(rb[p].w);
    }

    for (int i = 0; i < nch; i++) {
        __syncthreads();
        int cur = i & 1;
        if (i + 1 < nch) {
            int k0 = (i + 1) * 32;
            #pragma unroll
            for (int p = 0; p < 4; p++)
                ra[p] = *(const float4*)&A[(size_t)(bm + ar + 32*p) * K + k0 + ac4];
            #pragma unroll
            for (int p = 0; p < 4; p++)
                rb[p] = *(const float4*)&W[(size_t)(k0 + br + 8*p) * N + bn + bc4];
        }
        #pragma unroll
        for (int ks = 0; ks < 4; ks++) {
            int k = ks * 8;
            uint32_t a[4][4];
            #pragma unroll
            for (int mi = 0; mi < 4; mi++) {
                int m = wm * 64 + mi * 16 + gid;
                a[mi][0] = As[cur][m][k + tig];
                a[mi][1] = As[cur][m + 8][k + tig];
                a[mi][2] = As[cur][m][k + tig + 4];
                a[mi][3] = As[cur][m + 8][k + tig + 4];
            }
            #pragma unroll
            for (int ni = 0; ni < 4; ni++) {
                int n = wn * 32 + ni * 8 + gid;
                uint32_t b[2];
                b[0] = Bs[cur][k + tig][n];
                b[1] = Bs[cur][k + tig + 4][n];
                #pragma unroll
                for (int mi = 0; mi < 4; mi++)
                    mma_tf32(d[mi][ni], a[mi], b);
            }
        }
        if (i + 1 < nch) {
            int nxt = cur ^ 1;
            #pragma unroll
            for (int p = 0; p < 4; p++) {
                As[nxt][ar + 32*p][ac4+0] = f2tf32(ra[p].x); As[nxt][ar + 32*p][ac4+1] = f2tf32(ra[p].y);
                As[nxt][ar + 32*p][ac4+2] = f2tf32(ra[p].z); As[nxt][ar + 32*p][ac4+3] = f2tf32(ra[p].w);
            }
            #pragma unroll
            for (int p = 0; p < 4; p++) {
                Bs[nxt][br + 8*p][bc4+0] = f2tf32(rb[p].x); Bs[nxt][br + 8*p][bc4+1] = f2tf32(rb[p].y);
                Bs[nxt][br + 8*p][bc4+2] = f2tf32(rb[p].z); Bs[nxt][br + 8*p][bc4+3] = f2tf32(rb[p].w);
            }
        }
    }

    #pragma unroll
    for (int mi = 0; mi < 4; mi++) {
        int r0 = bm + wm * 64 + mi * 16 + gid;
        int r1 = r0 + 8;
        #pragma unroll
        for (int ni = 0; ni < 4; ni++) {
            int c = bn + wn * 32 + ni * 8 + tig * 2;
            float b0 = bias[c], b1 = bias[c + 1];
            float v00 = d[mi][ni][0] + b0, v01 = d[mi][ni][1] + b1;
            float v10 = d[mi][ni][2] + b0, v11 = d[mi][ni][3] + b1;
            if (resid) {
                const float2 rA = *(const float2*)&resid[(size_t)r0 * N + c];
                const float2 rB = *(const float2*)&resid[(size_t)r1 * N + c];
                v00 += rA.x; v01 += rA.y; v10 += rB.x; v11 += rB.y;
            }
            *(float2*)&C[(size_t)r0 * N + c] = make_float2(v00, v01);
            *(float2*)&C[(size_t)r1 * N + c] = make_float2(v10, v11);
        }
    }
}

// ---------------- fused attention, tf32 MMA, 512 threads (R11 config) ------
#define QROWS 32
#define MCHUNK 128
#define QPITCH 76
#define PF_STRIDE 33
#define PF_HALF 16896
#define P_FLOATS (2*PF_HALF)
#define SROW(r) ((r) < 16 ? (r)*1028 : PF_HALF + ((r)-16)*1028)
#define ATTN_SMEM_BYTES ((P_FLOATS + QROWS*QPITCH + 2*MCHUNK*QPITCH) * 4)
#define ATHR 512

__device__ __forceinline__ void fill_kv(uint32_t* __restrict__ dst,
                                        const float* __restrict__ src,
                                        int b, int base, int h, int tid) {
    #pragma unroll
    for (int p = 0; p < 4; p++) {
        int i = tid + p * ATHR;
        int r = i >> 4, c4 = (i & 15) * 4;
        float4 v = *(const float4*)&src[(size_t)(b * T_ + base + r) * D_ + h * DH_ + c4];
        uint4 u;
        u.x = f2tf32(v.x); u.y = f2tf32(v.y); u.z = f2tf32(v.z); u.w = f2tf32(v.w);
        *(uint4*)&dst[r*QPITCH + c4] = u;
    }
}

__global__ void attn_kernel(const float* __restrict__ qb,
                            const float* __restrict__ kb,
                            const float* __restrict__ vb,
                            const float* __restrict__ mask,
                            float* __restrict__ sbuf,
                            float* __restrict__ yb) {
    extern __shared__ float sm[];
    float*    P   = sm;
    uint32_t* Qs  = (uint32_t*)(sm + P_FLOATS);
    uint32_t* KV0 = Qs + QROWS * QPITCH;
    uint32_t* KV1 = KV0 + MCHUNK * QPITCH;
    float* rowinv = (float*)Qs;

    int h = blockIdx.y, b = blockIdx.z;
    int n0 = blockIdx.x * QROWS;
    int tid = threadIdx.x;
    int warp = tid >> 5, lane = tid & 31;
    int gid = lane >> 2, tig = lane & 3;
    const float invs = 0.125f;

    // stage Q tile 32x64 -> smem (packed STS.128)
    {
        int r = tid >> 4, c4 = (tid & 15) * 4;
        float4 v = *(const float4*)&qb[(size_t)(b * T_ + n0 + r) * D_ + h * DH_ + c4];
        uint4 u;
        u.x = f2tf32(v.x); u.y = f2tf32(v.y); u.z = f2tf32(v.z); u.w = f2tf32(v.w);
        *(uint4*)&Qs[r*QPITCH + c4] = u;
    }
    fill_kv(KV0, kb, b, 0, h, tid);
    __syncthreads();

    // hoist Q fragments to registers
    int wqm = warp >> 3, wqn = warp & 7;
    uint32_t qf[8][4];
    {
        int m = wqm * 16 + gid;
        #pragma unroll
        for (int ks = 0; ks < 8; ks++) {
            qf[ks][0] = Qs[m*QPITCH + ks*8 + tig];
            qf[ks][1] = Qs[(m+8)*QPITCH + ks*8 + tig];
            qf[ks][2] = Qs[m*QPITCH + ks*8 + tig + 4];
            qf[ks][3] = Qs[(m+8)*QPITCH + ks*8 + tig + 4];
        }
    }

    // per-warp row bases
    int r0 = wqm * 16 + gid, r1 = r0 + 8;
    const float* mrow0 = mask + (size_t)(b * T_ + n0 + r0) * T_;
    const float* mrow1 = mask + (size_t)(b * T_ + n0 + r1) * T_;
    float* sb0 = sbuf + ((((size_t)b * H_ + h) * T_ + n0 + r0) * T_);
    float* sb1 = sbuf + ((((size_t)b * H_ + h) * T_ + n0 + r1) * T_);
    float* s0 = P + SROW(r0);
    float* s1 = P + SROW(r1);

    // ---- QK^T ---- warp tile 16x16, double-buffered K, mask prefetched
    #pragma unroll 1
    for (int ci = 0; ci < T_ / MCHUNK; ci++) {
        if (ci) __syncthreads();
        uint32_t* cur = (ci & 1) ? KV1 : KV0;
        int mc = ci * MCHUNK;
        int mbase = mc + wqn * 16 + tig * 2;
        float2 mk0[2], mk1[2];
        mk0[0] = *(const float2*)&mrow0[mbase];
        mk1[0] = *(const float2*)&mrow1[mbase];
        mk0[1] = *(const float2*)&mrow0[mbase + 8];
        mk1[1] = *(const float2*)&mrow1[mbase + 8];
        if (ci + 1 < T_ / MCHUNK)
            fill_kv((ci & 1) ? KV0 : KV1, kb, b, (ci + 1) * MCHUNK, h, tid);

        float d[2][4] = {};
        #pragma unroll
        for (int ks = 0; ks < 8; ks++) {
            int k = ks * 8;
            #pragma unroll
            for (int ni = 0; ni < 2; ni++) {
                int n = wqn * 16 + ni * 8 + gid;
                uint32_t bb[2];
                bb[0] = cur[n*QPITCH + k + tig];
                bb[1] = cur[n*QPITCH + k + tig + 4];
                mma_tf32(d[ni], qf[ks], bb);
            }
        }
        #pragma unroll
        for (int ni = 0; ni < 2; ni++) {
            int m = mbase + ni * 8;
            float v00 = d[ni][0] * invs * mk0[ni].x, v01 = d[ni][1] * invs * mk0[ni].y;
            float v10 = d[ni][2] * invs * mk1[ni].x, v11 = d[ni][3] * invs * mk1[ni].y;
            *(float2*)&s0[m] = make_float2(v00, v01);
            *(float2*)&s1[m] = make_float2(v10, v11);
            *(float2*)&sb0[m] = make_float2(v00, v01);
            *(float2*)&sb1[m] = make_float2(v10, v11);
        }
        __syncthreads();
    }
    fill_kv(KV0, vb, b, 0, h, tid);
    __syncthreads();

    // ---- softmax: row-pair per warp; STS.64 quad halves to Pf ----
    {
        int half = warp >> 3, pp = warp & 7;
        const float* rlo = P + SROW(half * 16 + pp);
        const float* rhi = P + SROW(half * 16 + pp + 8);
        float2 buf[32];
        float suml = 0.f, sumh = 0.f;
        #pragma unroll
        for (int it = 0; it < 8; it++) {
            int c = it * 128 + lane * 4;
            float4 lo = *(const float4*)&rlo[c];
            float4 hi = *(const float4*)&rhi[c];
            float el0 = __expf(lo.x), el1 = __expf(lo.y), el2 = __expf(lo.z), el3 = __expf(lo.w);
            float eh0 = __expf(hi.x), eh1 = __expf(hi.y), eh2 = __expf(hi.z), eh3 = __expf(hi.w);
            suml += (el0 + el1) + (el2 + el3);
            sumh += (eh0 + eh1) + (eh2 + eh3);
            buf[it*4+0] = make_float2(__uint_as_float(f2tf32(el0)), __uint_as_float(f2tf32(eh0)));
            buf[it*4+1] = make_float2(__uint_as_float(f2tf32(el1)), __uint_as_float(f2tf32(eh1)));
            buf[it*4+2] = make_float2(__uint_as_float(f2tf32(el2)), __uint_as_float(f2tf32(eh2)));
            buf[it*4+3] = make_float2(__uint_as_float(f2tf32(el3)), __uint_as_float(f2tf32(eh3)));
        }
        #pragma unroll
        for (int o = 16; o > 0; o >>= 1) {
            suml += __shfl_xor_sync(0xffffffff, suml, o);
            sumh += __shfl_xor_sync(0xffffffff, sumh, o);
        }
        if (lane == 0) {
            rowinv[half * 16 + pp]     = 1.f / suml;
            rowinv[half * 16 + pp + 8] = 1.f / sumh;
        }
        __syncthreads();
        float* pf = P + half * PF_HALF;
        int eoff = (lane & 1) * 2;
        #pragma unroll
        for (int it = 0; it < 8; it++) {
            int g = it * 16 + (lane >> 1);
            float* qb_ = pf + (g * PF_STRIDE + pp * 4) * 4 + eoff;
            *(float2*)&qb_[0]  = buf[it*4+0];
            *(float2*)&qb_[4]  = buf[it*4+1];
            *(float2*)&qb_[8]  = buf[it*4+2];
            *(float2*)&qb_[12] = buf[it*4+3];
        }
    }
    __syncthreads();

    // ---- PV ---- warp tile 16x8; A via single LDS.128 from Pf
    int wpm = warp >> 3, wpn = warp & 7;
    const float* pfp = P + wpm * PF_HALF;
    float dy[4] = {};
    #pragma unroll 1
    for (int ci = 0; ci < T_ / MCHUNK; ci++) {
        uint32_t* cur = (ci & 1) ? KV1 : KV0;
        if (ci + 1 < T_ / MCHUNK)
            fill_kv((ci & 1) ? KV0 : KV1, vb, b, (ci + 1) * MCHUNK, h, tid);
        #pragma unroll 4
        for (int ks = 0; ks < 16; ks++) {
            int g = ci * 16 + ks;
            float4 aq = *(const float4*)&pfp[(g * PF_STRIDE + lane) * 4];
            uint32_t a[4];
            a[0] = __float_as_uint(aq.x); a[1] = __float_as_uint(aq.y);
            a[2] = __float_as_uint(aq.z); a[3] = __float_as_uint(aq.w);
            int k = ks * 8;
            int n = wpn * 8 + gid;
            uint32_t bb[2];
            bb[0] = cur[(k + tig)*QPITCH + n];
            bb[1] = cur[(k + tig + 4)*QPITCH + n];
            mma_tf32(dy, a, bb);
        }
        __syncthreads();
    }
    {
        int lr0 = wpm * 16 + gid, lr1 = lr0 + 8;
        float inv0 = rowinv[lr0], inv1 = rowinv[lr1];
        int rr0 = n0 + lr0, rr1 = n0 + lr1;
        int c = h * DH_ + wpn * 8 + tig * 2;
        *(float2*)&yb[(size_t)(b * T_ + rr0) * D_ + c] = make_float2(dy[0]*inv0, dy[1]*inv0);
        *(float2*)&yb[(size_t)(b * T_ + rr1) * D_ + c] = make_float2(dy[2]*inv1, dy[3]*inv1);
    }
}

// ---------------- transpose [b,h,n,m] -> [b,n,m,h] ----------------
__global__ void transpose_attn(const float* __restrict__ sbuf,
                               float* __restrict__ attn) {
    int n = blockIdx.x * 2 + (threadIdx.x >> 8);
    int b = blockIdx.y;
    int m4 = (threadIdx.x & 255) * 4;
    float v[8][4];
    #pragma unroll
    for (int h = 0; h < H_; h++) {
        float4 t = __ldg((const float4*)&sbuf[((((size_t)b * H_ + h) * T_ + n) * T_) + m4]);
        v[h][0] = t.x; v[h][1] = t.y; v[h][2] = t.z; v[h][3] = t.w;
    }
    float* obase = attn + (((size_t)(b * T_ + n) * T_ + m4)) * H_;
    #pragma unroll
    for (int j = 0; j < 4; j++) {
        float4* o = (float4*)(obase + j * H_);
        o[0] = make_float4(v[0][j], v[1][j], v[2][j], v[3][j]);
        o[1] = make_float4(v[4][j], v[5][j], v[6][j], v[7][j]);
    }
}

// ---------------- emb path: partial GEMV over t-chunks ----------------
__global__ void emb_partial(const float* __restrict__ emb,
                            const float* __restrict__ w,
                            float* __restrict__ part) {
    int c = blockIdx.x, b = blockIdx.y;
    int j = threadIdx.x;
    __shared__ float se[256];
    if (j < 256) {
        float e = emb[(size_t)b * TE_ + c * 256 + j];
        se[j] = __fdividef(e, 1.f + __expf(-e));
    }
    __syncthreads();
    float acc = 0.f;
    const float* wb = w + (size_t)(c * 256) * (2 * D_) + j;
    #pragma unroll 8
    for (int t = 0; t < 256; t++)
        acc += se[t] * wb[(size_t)t * (2 * D_)];
    part[((size_t)(b * 8 + c)) * (2 * D_) + j] = acc;
}

__global__ void emb_reduce(const float* __restrict__ part,
                           const float* __restrict__ bias,
                           float* __restrict__ out) {
    int b = blockIdx.x, j = threadIdx.x;
    float acc = bias[j];
    #pragma unroll
    for (int c = 0; c < 8; c++)
        acc += part[((size_t)(b * 8 + c)) * (2 * D_) + j];
    out[(size_t)b * (2 * D_) + j] = acc;
}

// ---------------- stylization ----------------
__global__ void styl_kernel(const float* __restrict__ y,
                            const float* __restrict__ g,
                            const float* __restrict__ bta,
                            const float* __restrict__ embout,
                            float* __restrict__ out) {
    int row = blockIdx.x;
    int b = row / T_;
    const float* yr = y + (size_t)row * D_;
    int tid = threadIdx.x;
    float v0 = yr[tid], v1 = yr[tid + 256];
    float s = v0 + v1, sq = v0*v0 + v1*v1;
    __shared__ float sh_s[8], sh_q[8];
    for (int o = 16; o > 0; o >>= 1) {
        s  += __shfl_xor_sync(0xffffffff, s,  o);
        sq += __shfl_xor_sync(0xffffffff, sq, o);
    }
    int warp = tid >> 5, lane = tid & 31;
    if (lane == 0) { sh_s[warp] = s; sh_q[warp] = sq; }
    __syncthreads();
    if (warp == 0) {
        s  = (lane < 8) ? sh_s[lane] : 0.f;
        sq = (lane < 8) ? sh_q[lane] : 0.f;
        for (int o = 4; o > 0; o >>= 1) {
            s  += __shfl_xor_sync(0xffffffff, s,  o);
            sq += __shfl_xor_sync(0xffffffff, sq, o);
        }
        if (lane == 0) { sh_s[0] = s; sh_q[0] = sq; }
    }
    __syncthreads();
    float mean = sh_s[0] * (1.f / D_);
    float var  = sh_q[0] * (1.f / D_) - mean * mean;
    float rs = rsqrtf(var + 1e-5f);
    const float* eo = embout + (size_t)b * (2 * D_);
    float* orow = out + (size_t)row * D_;
    {
        int c = tid;
        float ln = (v0 - mean) * rs * g[c] + bta[c];
        float hh = ln * (1.f + eo[c]) + eo[D_ + c];
        orow[c] = __fdividef(hh, 1.f + __expf(-hh));
    }
    {
        int c = tid + 256;
        float ln = (v1 - mean) * rs * g[c] + bta[c];
        float hh = ln * (1.f + eo[c]) + eo[D_ + c];
        orow[c] = __fdividef(hh, 1.f + __expf(-hh));
    }
}

// ---------------- launch ----------------
// Persistent side-stream + events for fork/join graph capture. Created once on
// the first (uncaptured) correctness call; the WORK per call is identical every
// time (same kernels, same deps), so determinism holds.
static cudaStream_t g_s2 = nullptr;
static cudaEvent_t g_ev_root = nullptr, g_ev_emb = nullptr,
                   g_ev_attn = nullptr, g_ev_tr = nullptr;

extern "C" void kernel_launch(void* const* d_in, const int* in_sizes, int n_in,
                              void* d_out, int out_size) {
    const float* x      = (const float*)d_in[0];
    const float* emb    = (const float*)d_in[1];
    const float* mask   = (const float*)d_in[2];
    const float* ln_g   = (const float*)d_in[3];
    const float* ln_b   = (const float*)d_in[4];
    const float* wq     = (const float*)d_in[5];
    const float* bq     = (const float*)d_in[6];
    const float* wk     = (const float*)d_in[7];
    const float* bk     = (const float*)d_in[8];
    const float* wv     = (const float*)d_in[9];
    const float* bv     = (const float*)d_in[10];
    const float* sb_g   = (const float*)d_in[11];
    const float* sb_b   = (const float*)d_in[12];
    const float* emb_w  = (const float*)d_in[13];
    const float* emb_b  = (const float*)d_in[14];
    const float* out_w  = (const float*)d_in[15];
    const float* out_b  = (const float*)d_in[16];

    float* out0 = (float*)d_out;                       // x + h : [4,1024,512]
    float* attn = out0 + (size_t)NTOK * D_;            // attention : [4,1024,1024,8]

    float *xn, *q, *k, *v, *y, *hb, *eo, *ep, *sb;
    cudaGetSymbolAddress((void**)&xn, g_xn);
    cudaGetSymbolAddress((void**)&q,  g_q);
    cudaGetSymbolAddress((void**)&k,  g_k);
    cudaGetSymbolAddress((void**)&v,  g_v);
    cudaGetSymbolAddress((void**)&y,  g_y);
    cudaGetSymbolAddress((void**)&hb, g_h);
    cudaGetSymbolAddress((void**)&eo, g_embout);
    cudaGetSymbolAddress((void**)&ep, g_embpart);
    cudaGetSymbolAddress((void**)&sb, g_sbuf);

    if (g_s2 == nullptr) {
        cudaStreamCreateWithFlags(&g_s2, cudaStreamNonBlocking);
        cudaEventCreateWithFlags(&g_ev_root, cudaEventDisableTiming);
        cudaEventCreateWithFlags(&g_ev_emb,  cudaEventDisableTiming);
        cudaEventCreateWithFlags(&g_ev_attn, cudaEventDisableTiming);
        cudaEventCreateWithFlags(&g_ev_tr,   cudaEventDisableTiming);
    }

    cudaFuncSetAttribute(attn_kernel, cudaFuncAttributeMaxDynamicSharedMemorySize,
                         ATTN_SMEM_BYTES);

    // fork: side stream runs the emb path (depends only on inputs)
    cudaEventRecord(g_ev_root, 0);
    cudaStreamWaitEvent(g_s2, g_ev_root, 0);
    emb_partial<<<dim3(8, B_), 1024, 0, g_s2>>>(emb, emb_w, ep);
    emb_reduce<<<B_, 1024, 0, g_s2>>>(ep, emb_b, eo);
    cudaEventRecord(g_ev_emb, g_s2);

    // main stream: ln -> QKV -> attn
    ln_kernel<<<NTOK, 256>>>(x, ln_g, ln_b, xn);
    dim3 gq(D_ / 128, NTOK / 128, 3);
    sgemm_tf32_128<<<gq, 256>>>(xn, wq, wk, wv, bq, bk, bv, q, k, v,
                                nullptr, NTOK, D_, D_);
    attn_kernel<<<dim3(T_ / QROWS, H_, B_), ATHR, ATTN_SMEM_BYTES>>>(q, k, v, mask, sb, y);

    // fork: transpose on side stream (needs sbuf only)
    cudaEventRecord(g_ev_attn, 0);
    cudaStreamWaitEvent(g_s2, g_ev_attn, 0);
    transpose_attn<<<dim3(T_ / 2, B_), 512, 0, g_s2>>>(sb, attn);
    cudaEventRecord(g_ev_tr, g_s2);

    // main stream: styl (needs y + eo) -> out GEMM; join emb first
    cudaStreamWaitEvent(0, g_ev_emb, 0);
    styl_kernel<<<NTOK, 256>>>(y, sb_g, sb_b, eo, hb);
    dim3 go(D_ / 128, NTOK / 128, 1);
    sgemm_tf32_128<<<go, 256>>>(hb, out_w, out_w, out_w, out_b, out_b, out_b,
                                out0, out0, out0, x, NTOK, D_, D_);

    // join transpose
    cudaStreamWaitEvent(0, g_ev_tr, 0);
}

// round 14
// speedup vs baseline: 1.1048x; 1.0450x over previous
#include <cuda_runtime.h>
#include <math.h>
#include <stdint.h>

#define B_ 4
#define T_ 1024
#define D_ 512
#define H_ 8
#define DH_ 64
#define TE_ 2048
#define NTOK (B_*T_)

// ---------------- scratch ----------------
__device__ float g_xn[NTOK * D_];
__device__ float g_q [NTOK * D_];
__device__ float g_k [NTOK * D_];
__device__ float g_v [NTOK * D_];
__device__ float g_y [NTOK * D_];
__device__ float g_h [NTOK * D_];
__device__ float g_embout[B_ * 2 * D_];
__device__ float g_embpart[8 * B_ * 2 * D_];
__device__ float g_sbuf[(size_t)B_ * H_ * T_ * T_];   // scores [b,h,n,m]

// ---------------- helpers ----------------
__device__ __forceinline__ uint32_t f2tf32(float x) {
    uint32_t u;
    asm("cvt.rna.tf32.f32 %0, %1;" : "=r"(u) : "f"(x));
    return u;
}

__device__ __forceinline__ void mma_tf32(float d[4], const uint32_t a[4], const uint32_t b[2]) {
    asm volatile(
        "mma.sync.aligned.m16n8k8.row.col.f32.tf32.tf32.f32 "
        "{%0,%1,%2,%3}, {%4,%5,%6,%7}, {%8,%9}, {%0,%1,%2,%3};\n"
        : "+f"(d[0]), "+f"(d[1]), "+f"(d[2]), "+f"(d[3])
        : "r"(a[0]), "r"(a[1]), "r"(a[2]), "r"(a[3]), "r"(b[0]), "r"(b[1]));
}

// ---------------- layernorm ----------------
__global__ void ln_kernel(const float* __restrict__ x,
                          const float* __restrict__ g,
                          const float* __restrict__ b,
                          float* __restrict__ out) {
    int row = blockIdx.x;
    const float* xr = x + (size_t)row * D_;
    int tid = threadIdx.x;
    float v0 = xr[tid], v1 = xr[tid + 256];
    float s = v0 + v1, sq = v0*v0 + v1*v1;
    __shared__ float sh_s[8], sh_q[8];
    for (int o = 16; o > 0; o >>= 1) {
        s  += __shfl_xor_sync(0xffffffff, s,  o);
        sq += __shfl_xor_sync(0xffffffff, sq, o);
    }
    int warp = tid >> 5, lane = tid & 31;
    if (lane == 0) { sh_s[warp] = s; sh_q[warp] = sq; }
    __syncthreads();
    if (warp == 0) {
        s  = (lane < 8) ? sh_s[lane] : 0.f;
        sq = (lane < 8) ? sh_q[lane] : 0.f;
        for (int o = 4; o > 0; o >>= 1) {
            s  += __shfl_xor_sync(0xffffffff, s,  o);
            sq += __shfl_xor_sync(0xffffffff, sq, o);
        }
        if (lane == 0) { sh_s[0] = s; sh_q[0] = sq; }
    }
    __syncthreads();
    float mean = sh_s[0] * (1.f / D_);
    float var  = sh_q[0] * (1.f / D_) - mean * mean;
    float rs = rsqrtf(var + 1e-5f);
    float* orow = out + (size_t)row * D_;
    orow[tid]       = (v0 - mean) * rs * g[tid]       + b[tid];
    orow[tid + 256] = (v1 - mean) * rs * g[tid + 256] + b[tid + 256];
}

// ---------------- tf32 SGEMM 128x128, double-buffered ----------------
__global__ __launch_bounds__(256, 2)
void sgemm_tf32_128(const float* __restrict__ A,
                    const float* __restrict__ W0, const float* __restrict__ W1,
                    const float* __restrict__ W2,
                    const float* __restrict__ Bi0, const float* __restrict__ Bi1,
                    const float* __restrict__ Bi2,
                    float* __restrict__ C0, float* __restrict__ C1,
                    float* __restrict__ C2,
                    const float* __restrict__ resid,
                    int M, int N, int K) {
    __shared__ uint32_t As[2][128][36];
    __shared__ uint32_t Bs[2][32][136];
    int z = blockIdx.z;
    const float* W    = (z == 0) ? W0  : (z == 1) ? W1  : W2;
    const float* bias = (z == 0) ? Bi0 : (z == 1) ? Bi1 : Bi2;
    float*       C    = (z == 0) ? C0  : (z == 1) ? C1  : C2;

    int bm = blockIdx.y * 128, bn = blockIdx.x * 128;
    int tid = threadIdx.x;
    int warp = tid >> 5, lane = tid & 31;
    int gid = lane >> 2, tig = lane & 3;
    int wm = warp >> 2, wn = warp & 3;

    int ar = tid >> 3, ac4 = (tid & 7) * 4;
    int br = tid >> 5, bc4 = (tid & 31) * 4;

    float4 ra[4], rb[4];
    float d[4][4][4] = {};
    const int nch = K / 32;

    #pragma unroll
    for (int p = 0; p < 4; p++)
        ra[p] = *(const float4*)&A[(size_t)(bm + ar + 32*p) * K + ac4];
    #pragma unroll
    for (int p = 0; p < 4; p++)
        rb[p] = *(const float4*)&W[(size_t)(br + 8*p) * N + bn + bc4];
    #pragma unroll
    for (int p = 0; p < 4; p++) {
        As[0][ar + 32*p][ac4+0] = f2tf32(ra[p].x); As[0][ar + 32*p][ac4+1] = f2tf32(ra[p].y);
        As[0][ar + 32*p][ac4+2] = f2tf32(ra[p].z); As[0][ar + 32*p][ac4+3] = f2tf32(ra[p].w);
    }
    #pragma unroll
    for (int p = 0; p < 4; p++) {
        Bs[0][br + 8*p][bc4+0] = f2tf32(rb[p].x); Bs[0][br + 8*p][bc4+1] = f2tf32(rb[p].y);
        Bs[0][br + 8*p][bc4+2] = f2tf32(rb[p].z); Bs[0][br + 8*p][bc4+3] = f2tf32(rb[p].w);
    }

    for (int i = 0; i < nch; i++) {
        __syncthreads();
        int cur = i & 1;
        if (i + 1 < nch) {
            int k0 = (i + 1) * 32;
            #pragma unroll
            for (int p = 0; p < 4; p++)
                ra[p] = *(const float4*)&A[(size_t)(bm + ar + 32*p) * K + k0 + ac4];
            #pragma unroll
            for (int p = 0; p < 4; p++)
                rb[p] = *(const float4*)&W[(size_t)(k0 + br + 8*p) * N + bn + bc4];
        }
        #pragma unroll
        for (int ks = 0; ks < 4; ks++) {
            int k = ks * 8;
            uint32_t a[4][4];
            #pragma unroll
            for (int mi = 0; mi < 4; mi++) {
                int m = wm * 64 + mi * 16 + gid;
                a[mi][0] = As[cur][m][k + tig];
                a[mi][1] = As[cur][m + 8][k + tig];
                a[mi][2] = As[cur][m][k + tig + 4];
                a[mi][3] = As[cur][m + 8][k + tig + 4];
            }
            #pragma unroll
            for (int ni = 0; ni < 4; ni++) {
                int n = wn * 32 + ni * 8 + gid;
                uint32_t b[2];
                b[0] = Bs[cur][k + tig][n];
                b[1] = Bs[cur][k + tig + 4][n];
                #pragma unroll
                for (int mi = 0; mi < 4; mi++)
                    mma_tf32(d[mi][ni], a[mi], b);
            }
        }
        if (i + 1 < nch) {
            int nxt = cur ^ 1;
            #pragma unroll
            for (int p = 0; p < 4; p++) {
                As[nxt][ar + 32*p][ac4+0] = f2tf32(ra[p].x); As[nxt][ar + 32*p][ac4+1] = f2tf32(ra[p].y);
                As[nxt][ar + 32*p][ac4+2] = f2tf32(ra[p].z); As[nxt][ar + 32*p][ac4+3] = f2tf32(ra[p].w);
            }
            #pragma unroll
            for (int p = 0; p < 4; p++) {
                Bs[nxt][br + 8*p][bc4+0] = f2tf32(rb[p].x); Bs[nxt][br + 8*p][bc4+1] = f2tf32(rb[p].y);
                Bs[nxt][br + 8*p][bc4+2] = f2tf32(rb[p].z); Bs[nxt][br + 8*p][bc4+3] = f2tf32(rb[p].w);
            }
        }
    }

    #pragma unroll
    for (int mi = 0; mi < 4; mi++) {
        int r0 = bm + wm * 64 + mi * 16 + gid;
        int r1 = r0 + 8;
        #pragma unroll
        for (int ni = 0; ni < 4; ni++) {
            int c = bn + wn * 32 + ni * 8 + tig * 2;
            float b0 = bias[c], b1 = bias[c + 1];
            float v00 = d[mi][ni][0] + b0, v01 = d[mi][ni][1] + b1;
            float v10 = d[mi][ni][2] + b0, v11 = d[mi][ni][3] + b1;
            if (resid) {
                const float2 rA = *(const float2*)&resid[(size_t)r0 * N + c];
                const float2 rB = *(const float2*)&resid[(size_t)r1 * N + c];
                v00 += rA.x; v01 += rA.y; v10 += rB.x; v11 += rB.y;
            }
            *(float2*)&C[(size_t)r0 * N + c] = make_float2(v00, v01);
            *(float2*)&C[(size_t)r1 * N + c] = make_float2(v10, v11);
        }
    }
}

// ---------------- fused attention, tf32 MMA, 512 threads ----------------
// exp fused into QK epilogue: raw scores -> sbuf, exp(scores) -> Pf fragment
// layout directly (no S region, no separate softmax pass). Deterministic
// two-level row-sum reduction. One barrier per chunk.
#define QROWS 32
#define MCHUNK 128
#define QPITCH 76
#define PF_STRIDE 33
#define PF_HALF 16896                       // 128 g-quads * 33 * 4
#define PF_FLOATS (2*PF_HALF)               // 33792
#define QS_FLOATS (QROWS*QPITCH)            // 2432
#define KV_FLOATS (MCHUNK*QPITCH)           // 9728
#define ATTN_SMEM_FLOATS (PF_FLOATS + QS_FLOATS + 2*KV_FLOATS + 256 + 32)
#define ATTN_SMEM_BYTES (ATTN_SMEM_FLOATS*4)  // 223872 B
#define ATHR 512

__device__ __forceinline__ void fill_kv(uint32_t* __restrict__ dst,
                                        const float* __restrict__ src,
                                        int b, int base, int h, int tid) {
    #pragma unroll
    for (int p = 0; p < 4; p++) {
        int i = tid + p * ATHR;
        int r = i >> 4, c4 = (i & 15) * 4;
        float4 v = *(const float4*)&src[(size_t)(b * T_ + base + r) * D_ + h * DH_ + c4];
        uint4 u;
        u.x = f2tf32(v.x); u.y = f2tf32(v.y); u.z = f2tf32(v.z); u.w = f2tf32(v.w);
        *(uint4*)&dst[r*QPITCH + c4] = u;
    }
}

__global__ void attn_kernel(const float* __restrict__ qb,
                            const float* __restrict__ kb,
                            const float* __restrict__ vb,
                            const float* __restrict__ mask,
                            float* __restrict__ sbuf,
                            float* __restrict__ yb) {
    extern __shared__ float sm[];
    float*    Pf  = sm;                              // 33792
    uint32_t* Qs  = (uint32_t*)(sm + PF_FLOATS);     // 2432
    uint32_t* KV0 = Qs + QS_FLOATS;                  // 9728
    uint32_t* KV1 = KV0 + KV_FLOATS;                 // 9728
    float* rowsumP = (float*)(KV1 + KV_FLOATS);      // [8][32]
    float* rowinv  = rowsumP + 256;                  // [32]

    int h = blockIdx.y, b = blockIdx.z;
    int n0 = blockIdx.x * QROWS;
    int tid = threadIdx.x;
    int warp = tid >> 5, lane = tid & 31;
    int gid = lane >> 2, tig = lane & 3;
    const float invs = 0.125f;

    // stage Q tile 32x64 -> smem (packed STS.128)
    {
        int r = tid >> 4, c4 = (tid & 15) * 4;
        float4 v = *(const float4*)&qb[(size_t)(b * T_ + n0 + r) * D_ + h * DH_ + c4];
        uint4 u;
        u.x = f2tf32(v.x); u.y = f2tf32(v.y); u.z = f2tf32(v.z); u.w = f2tf32(v.w);
        *(uint4*)&Qs[r*QPITCH + c4] = u;
    }
    fill_kv(KV0, kb, b, 0, h, tid);
    __syncthreads();

    // hoist Q fragments to registers
    int wqm = warp >> 3, wqn = warp & 7;
    uint32_t qf[8][4];
    {
        int m = wqm * 16 + gid;
        #pragma unroll
        for (int ks = 0; ks < 8; ks++) {
            qf[ks][0] = Qs[m*QPITCH + ks*8 + tig];
            qf[ks][1] = Qs[(m+8)*QPITCH + ks*8 + tig];
            qf[ks][2] = Qs[m*QPITCH + ks*8 + tig + 4];
            qf[ks][3] = Qs[(m+8)*QPITCH + ks*8 + tig + 4];
        }
    }

    // per-warp row bases
    int r0 = wqm * 16 + gid, r1 = r0 + 8;
    const float* mrow0 = mask + (size_t)(b * T_ + n0 + r0) * T_;
    const float* mrow1 = mask + (size_t)(b * T_ + n0 + r1) * T_;
    float* sb0 = sbuf + ((((size_t)b * H_ + h) * T_ + n0 + r0) * T_);
    float* sb1 = sbuf + ((((size_t)b * H_ + h) * T_ + n0 + r1) * T_);

    // Pf scatter constants (C-frag -> A-frag mapping)
    float* pfh = Pf + wqm * PF_HALF;
    int ebase = (tig >= 2) ? 2 : 0;
    int ql0 = gid * 4 + ((2 * tig) & 3);
    int ql1 = gid * 4 + ((2 * tig + 1) & 3);

    float sum0 = 0.f, sum1 = 0.f;

    // ---- QK^T + fused exp/scatter ---- 1 barrier per chunk
    #pragma unroll 1
    for (int ci = 0; ci < T_ / MCHUNK; ci++) {
        if (ci) __syncthreads();              // cur filled; next buffer free
        uint32_t* cur = (ci & 1) ? KV1 : KV0;
        int mbase = ci * MCHUNK + wqn * 16 + tig * 2;
        float2 mk0[2], mk1[2];
        mk0[0] = *(const float2*)&mrow0[mbase];
        mk1[0] = *(const float2*)&mrow1[mbase];
        mk0[1] = *(const float2*)&mrow0[mbase + 8];
        mk1[1] = *(const float2*)&mrow1[mbase + 8];
        if (ci + 1 < T_ / MCHUNK)
            fill_kv((ci & 1) ? KV0 : KV1, kb, b, (ci + 1) * MCHUNK, h, tid);

        float d[2][4] = {};
        #pragma unroll
        for (int ks = 0; ks < 8; ks++) {
            int k = ks * 8;
            #pragma unroll
            for (int ni = 0; ni < 2; ni++) {
                int n = wqn * 16 + ni * 8 + gid;
                uint32_t bb[2];
                bb[0] = cur[n*QPITCH + k + tig];
                bb[1] = cur[n*QPITCH + k + tig + 4];
                mma_tf32(d[ni], qf[ks], bb);
            }
        }
        #pragma unroll
        for (int ni = 0; ni < 2; ni++) {
            int m = mbase + ni * 8;
            float v00 = d[ni][0] * invs * mk0[ni].x, v01 = d[ni][1] * invs * mk0[ni].y;
            float v10 = d[ni][2] * invs * mk1[ni].x, v11 = d[ni][3] * invs * mk1[ni].y;
            *(float2*)&sb0[m] = make_float2(v00, v01);   // raw scores out
            *(float2*)&sb1[m] = make_float2(v10, v11);
            float e00 = __expf(v00), e01 = __expf(v01);
            float e10 = __expf(v10), e11 = __expf(v11);
            sum0 += e00 + e01;
            sum1 += e10 + e11;
            int g = ci * 16 + wqn * 2 + ni;
            float2 p0 = make_float2(__uint_as_float(f2tf32(e00)), __uint_as_float(f2tf32(e10)));
            float2 p1 = make_float2(__uint_as_float(f2tf32(e01)), __uint_as_float(f2tf32(e11)));
            *(float2*)&pfh[(g * PF_STRIDE + ql0) * 4 + ebase] = p0;
            *(float2*)&pfh[(g * PF_STRIDE + ql1) * 4 + ebase] = p1;
        }
    }

    // V chunk 0 prefetch (KV0 last read at ci=6; ci=7 used KV1)
    fill_kv(KV0, vb, b, 0, h, tid);

    // deterministic row sums: quad reduce -> per-warp partial -> smem
    sum0 += __shfl_xor_sync(0xffffffff, sum0, 1);
    sum0 += __shfl_xor_sync(0xffffffff, sum0, 2);
    sum1 += __shfl_xor_sync(0xffffffff, sum1, 1);
    sum1 += __shfl_xor_sync(0xffffffff, sum1, 2);
    if (tig == 0) {
        rowsumP[wqn * 32 + r0] = sum0;
        rowsumP[wqn * 32 + r1] = sum1;
    }
    __syncthreads();                          // Pf + partials + V0 visible
    if (tid < 32) {
        float s = 0.f;
        #pragma unroll
        for (int w = 0; w < 8; w++) s += rowsumP[w * 32 + tid];
        rowinv[tid] = 1.f / s;
    }

    // ---- PV ---- warp tile 16x8; A via single LDS.128 from Pf
    int wpm = warp >> 3, wpn = warp & 7;
    const float* pfp = Pf + wpm * PF_HALF;
    float dy[4] = {};
    #pragma unroll 1
    for (int ci = 0; ci < T_ / MCHUNK; ci++) {
        uint32_t* cur = (ci & 1) ? KV1 : KV0;
        if (ci + 1 < T_ / MCHUNK)
            fill_kv((ci & 1) ? KV0 : KV1, vb, b, (ci + 1) * MCHUNK, h, tid);
        #pragma unroll 4
        for (int ks = 0; ks < 16; ks++) {
            int g = ci * 16 + ks;
            float4 aq = *(const float4*)&pfp[(g * PF_STRIDE + lane) * 4];
            uint32_t a[4];
            a[0] = __float_as_uint(aq.x); a[1] = __float_as_uint(aq.y);
            a[2] = __float_as_uint(aq.z); a[3] = __float_as_uint(aq.w);
            int k = ks * 8;
            int n = wpn * 8 + gid;
            uint32_t bb[2];
            bb[0] = cur[(k + tig)*QPITCH + n];
            bb[1] = cur[(k + tig + 4)*QPITCH + n];
            mma_tf32(dy, a, bb);
        }
        __syncthreads();                      // next-chunk fill complete
    }
    {
        int lr0 = wpm * 16 + gid, lr1 = lr0 + 8;
        float inv0 = rowinv[lr0], inv1 = rowinv[lr1];
        int rr0 = n0 + lr0, rr1 = n0 + lr1;
        int c = h * DH_ + wpn * 8 + tig * 2;
        *(float2*)&yb[(size_t)(b * T_ + rr0) * D_ + c] = make_float2(dy[0]*inv0, dy[1]*inv0);
        *(float2*)&yb[(size_t)(b * T_ + rr1) * D_ + c] = make_float2(dy[2]*inv1, dy[3]*inv1);
    }
}

// ---------------- transpose [b,h,n,m] -> [b,n,m,h] ----------------
__global__ void transpose_attn(const float* __restrict__ sbuf,
                               float* __restrict__ attn) {
    int n = blockIdx.x * 2 + (threadIdx.x >> 8);
    int b = blockIdx.y;
    int m4 = (threadIdx.x & 255) * 4;
    float v[8][4];
    #pragma unroll
    for (int h = 0; h < H_; h++) {
        float4 t = __ldg((const float4*)&sbuf[((((size_t)b * H_ + h) * T_ + n) * T_) + m4]);
        v[h][0] = t.x; v[h][1] = t.y; v[h][2] = t.z; v[h][3] = t.w;
    }
    float* obase = attn + (((size_t)(b * T_ + n) * T_ + m4)) * H_;
    #pragma unroll
    for (int j = 0; j < 4; j++) {
        float4* o = (float4*)(obase + j * H_);
        o[0] = make_float4(v[0][j], v[1][j], v[2][j], v[3][j]);
        o[1] = make_float4(v[4][j], v[5][j], v[6][j], v[7][j]);
    }
}

// ---------------- emb path: partial GEMV over t-chunks ----------------
__global__ void emb_partial(const float* __restrict__ emb,
                            const float* __restrict__ w,
                            float* __restrict__ part) {
    int c = blockIdx.x, b = blockIdx.y;
    int j = threadIdx.x;
    __shared__ float se[256];
    if (j < 256) {
        float e = emb[(size_t)b * TE_ + c * 256 + j];
        se[j] = __fdividef(e, 1.f + __expf(-e));
    }
    __syncthreads();
    float acc = 0.f;
    const float* wb = w + (size_t)(c * 256) * (2 * D_) + j;
    #pragma unroll 8
    for (int t = 0; t < 256; t++)
        acc += se[t] * wb[(size_t)t * (2 * D_)];
    part[((size_t)(b * 8 + c)) * (2 * D_) + j] = acc;
}

__global__ void emb_reduce(const float* __restrict__ part,
                           const float* __restrict__ bias,
                           float* __restrict__ out) {
    int b = blockIdx.x, j = threadIdx.x;
    float acc = bias[j];
    #pragma unroll
    for (int c = 0; c < 8; c++)
        acc += part[((size_t)(b * 8 + c)) * (2 * D_) + j];
    out[(size_t)b * (2 * D_) + j] = acc;
}

// ---------------- stylization ----------------
__global__ void styl_kernel(const float* __restrict__ y,
                            const float* __restrict__ g,
                            const float* __restrict__ bta,
                            const float* __restrict__ embout,
                            float* __restrict__ out) {
    int row = blockIdx.x;
    int b = row / T_;
    const float* yr = y + (size_t)row * D_;
    int tid = threadIdx.x;
    float v0 = yr[tid], v1 = yr[tid + 256];
    float s = v0 + v1, sq = v0*v0 + v1*v1;
    __shared__ float sh_s[8], sh_q[8];
    for (int o = 16; o > 0; o >>= 1) {
        s  += __shfl_xor_sync(0xffffffff, s,  o);
        sq += __shfl_xor_sync(0xffffffff, sq, o);
    }
    int warp = tid >> 5, lane = tid & 31;
    if (lane == 0) { sh_s[warp] = s; sh_q[warp] = sq; }
    __syncthreads();
    if (warp == 0) {
        s  = (lane < 8) ? sh_s[lane] : 0.f;
        sq = (lane < 8) ? sh_q[lane] : 0.f;
        for (int o = 4; o > 0; o >>= 1) {
            s  += __shfl_xor_sync(0xffffffff, s,  o);
            sq += __shfl_xor_sync(0xffffffff, sq, o);
        }
        if (lane == 0) { sh_s[0] = s; sh_q[0] = sq; }
    }
    __syncthreads();
    float mean = sh_s[0] * (1.f / D_);
    float var  = sh_q[0] * (1.f / D_) - mean * mean;
    float rs = rsqrtf(var + 1e-5f);
    const float* eo = embout + (size_t)b * (2 * D_);
    float* orow = out + (size_t)row * D_;
    {
        int c = tid;
        float ln = (v0 - mean) * rs * g[c] + bta[c];
        float hh = ln * (1.f + eo[c]) + eo[D_ + c];
        orow[c] = __fdividef(hh, 1.f + __expf(-hh));
    }
    {
        int c = tid + 256;
        float ln = (v1 - mean) * rs * g[c] + bta[c];
        float hh = ln * (1.f + eo[c]) + eo[D_ + c];
        orow[c] = __fdividef(hh, 1.f + __expf(-hh));
    }
}

// ---------------- launch ----------------
static cudaStream_t g_s2 = nullptr;
static cudaEvent_t g_ev_root = nullptr, g_ev_emb = nullptr,
                   g_ev_attn = nullptr, g_ev_tr = nullptr;

extern "C" void kernel_launch(void* const* d_in, const int* in_sizes, int n_in,
                              void* d_out, int out_size) {
    const float* x      = (const float*)d_in[0];
    const float* emb    = (const float*)d_in[1];
    const float* mask   = (const float*)d_in[2];
    const float* ln_g   = (const float*)d_in[3];
    const float* ln_b   = (const float*)d_in[4];
    const float* wq     = (const float*)d_in[5];
    const float* bq     = (const float*)d_in[6];
    const float* wk     = (const float*)d_in[7];
    const float* bk     = (const float*)d_in[8];
    const float* wv     = (const float*)d_in[9];
    const float* bv     = (const float*)d_in[10];
    const float* sb_g   = (const float*)d_in[11];
    const float* sb_b   = (const float*)d_in[12];
    const float* emb_w  = (const float*)d_in[13];
    const float* emb_b  = (const float*)d_in[14];
    const float* out_w  = (const float*)d_in[15];
    const float* out_b  = (const float*)d_in[16];

    float* out0 = (float*)d_out;                       // x + h : [4,1024,512]
    float* attn = out0 + (size_t)NTOK * D_;            // attention : [4,1024,1024,8]

    float *xn, *q, *k, *v, *y, *hb, *eo, *ep, *sb;
    cudaGetSymbolAddress((void**)&xn, g_xn);
    cudaGetSymbolAddress((void**)&q,  g_q);
    cudaGetSymbolAddress((void**)&k,  g_k);
    cudaGetSymbolAddress((void**)&v,  g_v);
    cudaGetSymbolAddress((void**)&y,  g_y);
    cudaGetSymbolAddress((void**)&hb, g_h);
    cudaGetSymbolAddress((void**)&eo, g_embout);
    cudaGetSymbolAddress((void**)&ep, g_embpart);
    cudaGetSymbolAddress((void**)&sb, g_sbuf);

    if (g_s2 == nullptr) {
        cudaStreamCreateWithFlags(&g_s2, cudaStreamNonBlocking);
        cudaEventCreateWithFlags(&g_ev_root, cudaEventDisableTiming);
        cudaEventCreateWithFlags(&g_ev_emb,  cudaEventDisableTiming);
        cudaEventCreateWithFlags(&g_ev_attn, cudaEventDisableTiming);
        cudaEventCreateWithFlags(&g_ev_tr,   cudaEventDisableTiming);
    }

    cudaFuncSetAttribute(attn_kernel, cudaFuncAttributeMaxDynamicSharedMemorySize,
                         ATTN_SMEM_BYTES);

    // fork: emb path on side stream
    cudaEventRecord(g_ev_root, 0);
    cudaStreamWaitEvent(g_s2, g_ev_root, 0);
    emb_partial<<<dim3(8, B_), 1024, 0, g_s2>>>(emb, emb_w, ep);
    emb_reduce<<<B_, 1024, 0, g_s2>>>(ep, emb_b, eo);
    cudaEventRecord(g_ev_emb, g_s2);

    // main: ln -> QKV -> attn
    ln_kernel<<<NTOK, 256>>>(x, ln_g, ln_b, xn);
    dim3 gq(D_ / 128, NTOK / 128, 3);
    sgemm_tf32_128<<<gq, 256>>>(xn, wq, wk, wv, bq, bk, bv, q, k, v,
                                nullptr, NTOK, D_, D_);
    attn_kernel<<<dim3(T_ / QROWS, H_, B_), ATHR, ATTN_SMEM_BYTES>>>(q, k, v, mask, sb, y);

    // fork: transpose on side stream
    cudaEventRecord(g_ev_attn, 0);
    cudaStreamWaitEvent(g_s2, g_ev_attn, 0);
    transpose_attn<<<dim3(T_ / 2, B_), 512, 0, g_s2>>>(sb, attn);
    cudaEventRecord(g_ev_tr, g_s2);

    // main: styl -> out GEMM (join emb first)
    cudaStreamWaitEvent(0, g_ev_emb, 0);
    styl_kernel<<<NTOK, 256>>>(y, sb_g, sb_b, eo, hb);
    dim3 go(D_ / 128, NTOK / 128, 1);
    sgemm_tf32_128<<<go, 256>>>(hb, out_w, out_w, out_w, out_b, out_b, out_b,
                                out0, out0, out0, x, NTOK, D_, D_);

    cudaStreamWaitEvent(0, g_ev_tr, 0);
}

// round 15
// speedup vs baseline: 1.1125x; 1.0069x over previous
#include <cuda_runtime.h>
#include <math.h>
#include <stdint.h>

#define B_ 4
#define T_ 1024
#define D_ 512
#define H_ 8
#define DH_ 64
#define TE_ 2048
#define NTOK (B_*T_)

// ---------------- scratch ----------------
__device__ float g_xn[NTOK * D_];
__device__ float g_q [NTOK * D_];
__device__ float g_k [NTOK * D_];
__device__ float g_v [NTOK * D_];
__device__ float g_y [NTOK * D_];
__device__ float g_h [NTOK * D_];
__device__ float g_embout[B_ * 2 * D_];
__device__ float g_embpart[8 * B_ * 2 * D_];
__device__ float g_sbuf[(size_t)B_ * H_ * T_ * T_];   // scores [b,h,n,m]

// ---------------- helpers ----------------
__device__ __forceinline__ uint32_t f2tf32(float x) {
    uint32_t u;
    asm("cvt.rna.tf32.f32 %0, %1;" : "=r"(u) : "f"(x));
    return u;
}

__device__ __forceinline__ void mma_tf32(float d[4], const uint32_t a[4], const uint32_t b[2]) {
    asm volatile(
        "mma.sync.aligned.m16n8k8.row.col.f32.tf32.tf32.f32 "
        "{%0,%1,%2,%3}, {%4,%5,%6,%7}, {%8,%9}, {%0,%1,%2,%3};\n"
        : "+f"(d[0]), "+f"(d[1]), "+f"(d[2]), "+f"(d[3])
        : "r"(a[0]), "r"(a[1]), "r"(a[2]), "r"(a[3]), "r"(b[0]), "r"(b[1]));
}

// FFMA-pipe exp (no MUFU): exp(x) = 2^n * e^f
__device__ __forceinline__ float fexp(float x) {
    x = fmaxf(x, -80.f);
    float t = fmaf(x, 1.4426950408889634f, 12582912.0f);
    float n = t - 12582912.0f;
    float f = fmaf(n, -0.6931471805599453f, x);
    float p = 8.3333333e-3f;
    p = fmaf(p, f, 4.1666667e-2f);
    p = fmaf(p, f, 1.6666667e-1f);
    p = fmaf(p, f, 5.0e-1f);
    p = fmaf(p, f, 1.0f);
    p = fmaf(p, f, 1.0f);
    float scale = __int_as_float((__float_as_int(t) + 127) << 23);
    return p * scale;
}

// ---------------- layernorm ----------------
__global__ void ln_kernel(const float* __restrict__ x,
                          const float* __restrict__ g,
                          const float* __restrict__ b,
                          float* __restrict__ out) {
    int row = blockIdx.x;
    const float* xr = x + (size_t)row * D_;
    int tid = threadIdx.x;
    float v0 = xr[tid], v1 = xr[tid + 256];
    float s = v0 + v1, sq = v0*v0 + v1*v1;
    __shared__ float sh_s[8], sh_q[8];
    for (int o = 16; o > 0; o >>= 1) {
        s  += __shfl_xor_sync(0xffffffff, s,  o);
        sq += __shfl_xor_sync(0xffffffff, sq, o);
    }
    int warp = tid >> 5, lane = tid & 31;
    if (lane == 0) { sh_s[warp] = s; sh_q[warp] = sq; }
    __syncthreads();
    if (warp == 0) {
        s  = (lane < 8) ? sh_s[lane] : 0.f;
        sq = (lane < 8) ? sh_q[lane] : 0.f;
        for (int o = 4; o > 0; o >>= 1) {
            s  += __shfl_xor_sync(0xffffffff, s,  o);
            sq += __shfl_xor_sync(0xffffffff, sq, o);
        }
        if (lane == 0) { sh_s[0] = s; sh_q[0] = sq; }
    }
    __syncthreads();
    float mean = sh_s[0] * (1.f / D_);
    float var  = sh_q[0] * (1.f / D_) - mean * mean;
    float rs = rsqrtf(var + 1e-5f);
    float* orow = out + (size_t)row * D_;
    orow[tid]       = (v0 - mean) * rs * g[tid]       + b[tid];
    orow[tid + 256] = (v1 - mean) * rs * g[tid + 256] + b[tid + 256];
}

// ---------------- tf32 SGEMM 128x128, double-buffered ----------------
__global__ __launch_bounds__(256, 2)
void sgemm_tf32_128(const float* __restrict__ A,
                    const float* __restrict__ W0, const float* __restrict__ W1,
                    const float* __restrict__ W2,
                    const float* __restrict__ Bi0, const float* __restrict__ Bi1,
                    const float* __restrict__ Bi2,
                    float* __restrict__ C0, float* __restrict__ C1,
                    float* __restrict__ C2,
                    const float* __restrict__ resid,
                    int M, int N, int K) {
    __shared__ uint32_t As[2][128][36];
    __shared__ uint32_t Bs[2][32][136];
    int z = blockIdx.z;
    const float* W    = (z == 0) ? W0  : (z == 1) ? W1  : W2;
    const float* bias = (z == 0) ? Bi0 : (z == 1) ? Bi1 : Bi2;
    float*       C    = (z == 0) ? C0  : (z == 1) ? C1  : C2;

    int bm = blockIdx.y * 128, bn = blockIdx.x * 128;
    int tid = threadIdx.x;
    int warp = tid >> 5, lane = tid & 31;
    int gid = lane >> 2, tig = lane & 3;
    int wm = warp >> 2, wn = warp & 3;

    int ar = tid >> 3, ac4 = (tid & 7) * 4;
    int br = tid >> 5, bc4 = (tid & 31) * 4;

    float4 ra[4], rb[4];
    float d[4][4][4] = {};
    const int nch = K / 32;

    #pragma unroll
    for (int p = 0; p < 4; p++)
        ra[p] = *(const float4*)&A[(size_t)(bm + ar + 32*p) * K + ac4];
    #pragma unroll
    for (int p = 0; p < 4; p++)
        rb[p] = *(const float4*)&W[(size_t)(br + 8*p) * N + bn + bc4];
    #pragma unroll
    for (int p = 0; p < 4; p++) {
        As[0][ar + 32*p][ac4+0] = f2tf32(ra[p].x); As[0][ar + 32*p][ac4+1] = f2tf32(ra[p].y);
        As[0][ar + 32*p][ac4+2] = f2tf32(ra[p].z); As[0][ar + 32*p][ac4+3] = f2tf32(ra[p].w);
    }
    #pragma unroll
    for (int p = 0; p < 4; p++) {
        Bs[0][br + 8*p][bc4+0] = f2tf32(rb[p].x); Bs[0][br + 8*p][bc4+1] = f2tf32(rb[p].y);
        Bs[0][br + 8*p][bc4+2] = f2tf32(rb[p].z); Bs[0][br + 8*p][bc4+3] = f2tf32(rb[p].w);
    }

    for (int i = 0; i < nch; i++) {
        __syncthreads();
        int cur = i & 1;
        if (i + 1 < nch) {
            int k0 = (i + 1) * 32;
            #pragma unroll
            for (int p = 0; p < 4; p++)
                ra[p] = *(const float4*)&A[(size_t)(bm + ar + 32*p) * K + k0 + ac4];
            #pragma unroll
            for (int p = 0; p < 4; p++)
                rb[p] = *(const float4*)&W[(size_t)(k0 + br + 8*p) * N + bn + bc4];
        }
        #pragma unroll
        for (int ks = 0; ks < 4; ks++) {
            int k = ks * 8;
            uint32_t a[4][4];
            #pragma unroll
            for (int mi = 0; mi < 4; mi++) {
                int m = wm * 64 + mi * 16 + gid;
                a[mi][0] = As[cur][m][k + tig];
                a[mi][1] = As[cur][m + 8][k + tig];
                a[mi][2] = As[cur][m][k + tig + 4];
                a[mi][3] = As[cur][m + 8][k + tig + 4];
            }
            #pragma unroll
            for (int ni = 0; ni < 4; ni++) {
                int n = wn * 32 + ni * 8 + gid;
                uint32_t b[2];
                b[0] = Bs[cur][k + tig][n];
                b[1] = Bs[cur][k + tig + 4][n];
                #pragma unroll
                for (int mi = 0; mi < 4; mi++)
                    mma_tf32(d[mi][ni], a[mi], b);
            }
        }
        if (i + 1 < nch) {
            int nxt = cur ^ 1;
            #pragma unroll
            for (int p = 0; p < 4; p++) {
                As[nxt][ar + 32*p][ac4+0] = f2tf32(ra[p].x); As[nxt][ar + 32*p][ac4+1] = f2tf32(ra[p].y);
                As[nxt][ar + 32*p][ac4+2] = f2tf32(ra[p].z); As[nxt][ar + 32*p][ac4+3] = f2tf32(ra[p].w);
            }
            #pragma unroll
            for (int p = 0; p < 4; p++) {
                Bs[nxt][br + 8*p][bc4+0] = f2tf32(rb[p].x); Bs[nxt][br + 8*p][bc4+1] = f2tf32(rb[p].y);
                Bs[nxt][br + 8*p][bc4+2] = f2tf32(rb[p].z); Bs[nxt][br + 8*p][bc4+3] = f2tf32(rb[p].w);
            }
        }
    }

    #pragma unroll
    for (int mi = 0; mi < 4; mi++) {
        int r0 = bm + wm * 64 + mi * 16 + gid;
        int r1 = r0 + 8;
        #pragma unroll
        for (int ni = 0; ni < 4; ni++) {
            int c = bn + wn * 32 + ni * 8 + tig * 2;
            float b0 = bias[c], b1 = bias[c + 1];
            float v00 = d[mi][ni][0] + b0, v01 = d[mi][ni][1] + b1;
            float v10 = d[mi][ni][2] + b0, v11 = d[mi][ni][3] + b1;
            if (resid) {
                const float2 rA = *(const float2*)&resid[(size_t)r0 * N + c];
                const float2 rB = *(const float2*)&resid[(size_t)r1 * N + c];
                v00 += rA.x; v01 += rA.y; v10 += rB.x; v11 += rB.y;
            }
            *(float2*)&C[(size_t)r0 * N + c] = make_float2(v00, v01);
            *(float2*)&C[(size_t)r1 * N + c] = make_float2(v10, v11);
        }
    }
}

// ---------------- fused attention, tf32 MMA, 512 threads ----------------
// exp fused into QK epilogue; 50/50 MUFU(__expf) / FFMA(fexp) pipe balance.
#define QROWS 32
#define MCHUNK 128
#define QPITCH 76
#define PF_STRIDE 33
#define PF_HALF 16896
#define PF_FLOATS (2*PF_HALF)
#define QS_FLOATS (QROWS*QPITCH)
#define KV_FLOATS (MCHUNK*QPITCH)
#define ATTN_SMEM_FLOATS (PF_FLOATS + QS_FLOATS + 2*KV_FLOATS + 256 + 32)
#define ATTN_SMEM_BYTES (ATTN_SMEM_FLOATS*4)
#define ATHR 512

__device__ __forceinline__ void fill_kv(uint32_t* __restrict__ dst,
                                        const float* __restrict__ src,
                                        int b, int base, int h, int tid) {
    #pragma unroll
    for (int p = 0; p < 4; p++) {
        int i = tid + p * ATHR;
        int r = i >> 4, c4 = (i & 15) * 4;
        float4 v = *(const float4*)&src[(size_t)(b * T_ + base + r) * D_ + h * DH_ + c4];
        uint4 u;
        u.x = f2tf32(v.x); u.y = f2tf32(v.y); u.z = f2tf32(v.z); u.w = f2tf32(v.w);
        *(uint4*)&dst[r*QPITCH + c4] = u;
    }
}

__global__ void attn_kernel(const float* __restrict__ qb,
                            const float* __restrict__ kb,
                            const float* __restrict__ vb,
                            const float* __restrict__ mask,
                            float* __restrict__ sbuf,
                            float* __restrict__ yb) {
    extern __shared__ float sm[];
    float*    Pf  = sm;
    uint32_t* Qs  = (uint32_t*)(sm + PF_FLOATS);
    uint32_t* KV0 = Qs + QS_FLOATS;
    uint32_t* KV1 = KV0 + KV_FLOATS;
    float* rowsumP = (float*)(KV1 + KV_FLOATS);
    float* rowinv  = rowsumP + 256;

    int h = blockIdx.y, b = blockIdx.z;
    int n0 = blockIdx.x * QROWS;
    int tid = threadIdx.x;
    int warp = tid >> 5, lane = tid & 31;
    int gid = lane >> 2, tig = lane & 3;
    const float invs = 0.125f;

    // stage Q tile 32x64 -> smem
    {
        int r = tid >> 4, c4 = (tid & 15) * 4;
        float4 v = *(const float4*)&qb[(size_t)(b * T_ + n0 + r) * D_ + h * DH_ + c4];
        uint4 u;
        u.x = f2tf32(v.x); u.y = f2tf32(v.y); u.z = f2tf32(v.z); u.w = f2tf32(v.w);
        *(uint4*)&Qs[r*QPITCH + c4] = u;
    }
    fill_kv(KV0, kb, b, 0, h, tid);
    __syncthreads();

    // hoist Q fragments to registers
    int wqm = warp >> 3, wqn = warp & 7;
    uint32_t qf[8][4];
    {
        int m = wqm * 16 + gid;
        #pragma unroll
        for (int ks = 0; ks < 8; ks++) {
            qf[ks][0] = Qs[m*QPITCH + ks*8 + tig];
            qf[ks][1] = Qs[(m+8)*QPITCH + ks*8 + tig];
            qf[ks][2] = Qs[m*QPITCH + ks*8 + tig + 4];
            qf[ks][3] = Qs[(m+8)*QPITCH + ks*8 + tig + 4];
        }
    }

    // per-warp row bases
    int r0 = wqm * 16 + gid, r1 = r0 + 8;
    const float* mrow0 = mask + (size_t)(b * T_ + n0 + r0) * T_;
    const float* mrow1 = mask + (size_t)(b * T_ + n0 + r1) * T_;
    float* sb0 = sbuf + ((((size_t)b * H_ + h) * T_ + n0 + r0) * T_);
    float* sb1 = sbuf + ((((size_t)b * H_ + h) * T_ + n0 + r1) * T_);

    // Pf scatter constants (C-frag -> A-frag mapping)
    float* pfh = Pf + wqm * PF_HALF;
    int ebase = (tig >= 2) ? 2 : 0;
    int ql0 = gid * 4 + ((2 * tig) & 3);
    int ql1 = gid * 4 + ((2 * tig + 1) & 3);

    float sum0 = 0.f, sum1 = 0.f;

    // ---- QK^T + fused exp/scatter ---- 1 barrier per chunk
    #pragma unroll 1
    for (int ci = 0; ci < T_ / MCHUNK; ci++) {
        if (ci) __syncthreads();
        uint32_t* cur = (ci & 1) ? KV1 : KV0;
        int mbase = ci * MCHUNK + wqn * 16 + tig * 2;
        float2 mk0[2], mk1[2];
        mk0[0] = *(const float2*)&mrow0[mbase];
        mk1[0] = *(const float2*)&mrow1[mbase];
        mk0[1] = *(const float2*)&mrow0[mbase + 8];
        mk1[1] = *(const float2*)&mrow1[mbase + 8];
        if (ci + 1 < T_ / MCHUNK)
            fill_kv((ci & 1) ? KV0 : KV1, kb, b, (ci + 1) * MCHUNK, h, tid);

        float d[2][4] = {};
        #pragma unroll
        for (int ks = 0; ks < 8; ks++) {
            int k = ks * 8;
            #pragma unroll
            for (int ni = 0; ni < 2; ni++) {
                int n = wqn * 16 + ni * 8 + gid;
                uint32_t bb[2];
                bb[0] = cur[n*QPITCH + k + tig];
                bb[1] = cur[n*QPITCH + k + tig + 4];
                mma_tf32(d[ni], qf[ks], bb);
            }
        }
        #pragma unroll
        for (int ni = 0; ni < 2; ni++) {
            int m = mbase + ni * 8;
            float v00 = d[ni][0] * invs * mk0[ni].x, v01 = d[ni][1] * invs * mk0[ni].y;
            float v10 = d[ni][2] * invs * mk1[ni].x, v11 = d[ni][3] * invs * mk1[ni].y;
            *(float2*)&sb0[m] = make_float2(v00, v01);   // raw scores out
            *(float2*)&sb1[m] = make_float2(v10, v11);
            // 50/50 MUFU / FFMA-poly exp (pipe balance)
            float e00 = __expf(v00), e01 = fexp(v01);
            float e10 = fexp(v10),   e11 = __expf(v11);
            sum0 += e00 + e01;
            sum1 += e10 + e11;
            int g = ci * 16 + wqn * 2 + ni;
            float2 p0 = make_float2(__uint_as_float(f2tf32(e00)), __uint_as_float(f2tf32(e10)));
            float2 p1 = make_float2(__uint_as_float(f2tf32(e01)), __uint_as_float(f2tf32(e11)));
            *(float2*)&pfh[(g * PF_STRIDE + ql0) * 4 + ebase] = p0;
            *(float2*)&pfh[(g * PF_STRIDE + ql1) * 4 + ebase] = p1;
        }
    }

    // V chunk 0 prefetch
    fill_kv(KV0, vb, b, 0, h, tid);

    // deterministic row sums
    sum0 += __shfl_xor_sync(0xffffffff, sum0, 1);
    sum0 += __shfl_xor_sync(0xffffffff, sum0, 2);
    sum1 += __shfl_xor_sync(0xffffffff, sum1, 1);
    sum1 += __shfl_xor_sync(0xffffffff, sum1, 2);
    if (tig == 0) {
        rowsumP[wqn * 32 + r0] = sum0;
        rowsumP[wqn * 32 + r1] = sum1;
    }
    __syncthreads();
    if (tid < 32) {
        float s = 0.f;
        #pragma unroll
        for (int w = 0; w < 8; w++) s += rowsumP[w * 32 + tid];
        rowinv[tid] = 1.f / s;
    }

    // ---- PV ---- warp tile 16x8; A via single LDS.128 from Pf
    int wpm = warp >> 3, wpn = warp & 7;
    const float* pfp = Pf + wpm * PF_HALF;
    float dy[4] = {};
    #pragma unroll 1
    for (int ci = 0; ci < T_ / MCHUNK; ci++) {
        uint32_t* cur = (ci & 1) ? KV1 : KV0;
        if (ci + 1 < T_ / MCHUNK)
            fill_kv((ci & 1) ? KV0 : KV1, vb, b, (ci + 1) * MCHUNK, h, tid);
        #pragma unroll 4
        for (int ks = 0; ks < 16; ks++) {
            int g = ci * 16 + ks;
            float4 aq = *(const float4*)&pfp[(g * PF_STRIDE + lane) * 4];
            uint32_t a[4];
            a[0] = __float_as_uint(aq.x); a[1] = __float_as_uint(aq.y);
            a[2] = __float_as_uint(aq.z); a[3] = __float_as_uint(aq.w);
            int k = ks * 8;
            int n = wpn * 8 + gid;
            uint32_t bb[2];
            bb[0] = cur[(k + tig)*QPITCH + n];
            bb[1] = cur[(k + tig + 4)*QPITCH + n];
            mma_tf32(dy, a, bb);
        }
        __syncthreads();
    }
    {
        int lr0 = wpm * 16 + gid, lr1 = lr0 + 8;
        float inv0 = rowinv[lr0], inv1 = rowinv[lr1];
        int rr0 = n0 + lr0, rr1 = n0 + lr1;
        int c = h * DH_ + wpn * 8 + tig * 2;
        *(float2*)&yb[(size_t)(b * T_ + rr0) * D_ + c] = make_float2(dy[0]*inv0, dy[1]*inv0);
        *(float2*)&yb[(size_t)(b * T_ + rr1) * D_ + c] = make_float2(dy[2]*inv1, dy[3]*inv1);
    }
}

// ---------------- transpose [b,h,n,m] -> [b,n,m,h] ----------------
__global__ void transpose_attn(const float* __restrict__ sbuf,
                               float* __restrict__ attn) {
    int n = blockIdx.x * 2 + (threadIdx.x >> 8);
    int b = blockIdx.y;
    int m4 = (threadIdx.x & 255) * 4;
    float v[8][4];
    #pragma unroll
    for (int h = 0; h < H_; h++) {
        float4 t = __ldg((const float4*)&sbuf[((((size_t)b * H_ + h) * T_ + n) * T_) + m4]);
        v[h][0] = t.x; v[h][1] = t.y; v[h][2] = t.z; v[h][3] = t.w;
    }
    float* obase = attn + (((size_t)(b * T_ + n) * T_ + m4)) * H_;
    #pragma unroll
    for (int j = 0; j < 4; j++) {
        float4* o = (float4*)(obase + j * H_);
        o[0] = make_float4(v[0][j], v[1][j], v[2][j], v[3][j]);
        o[1] = make_float4(v[4][j], v[5][j], v[6][j], v[7][j]);
    }
}

// ---------------- emb path ----------------
__global__ void emb_partial(const float* __restrict__ emb,
                            const float* __restrict__ w,
                            float* __restrict__ part) {
    int c = blockIdx.x, b = blockIdx.y;
    int j = threadIdx.x;
    __shared__ float se[256];
    if (j < 256) {
        float e = emb[(size_t)b * TE_ + c * 256 + j];
        se[j] = __fdividef(e, 1.f + __expf(-e));
    }
    __syncthreads();
    float acc = 0.f;
    const float* wb = w + (size_t)(c * 256) * (2 * D_) + j;
    #pragma unroll 8
    for (int t = 0; t < 256; t++)
        acc += se[t] * wb[(size_t)t * (2 * D_)];
    part[((size_t)(b * 8 + c)) * (2 * D_) + j] = acc;
}

__global__ void emb_reduce(const float* __restrict__ part,
                           const float* __restrict__ bias,
                           float* __restrict__ out) {
    int b = blockIdx.x, j = threadIdx.x;
    float acc = bias[j];
    #pragma unroll
    for (int c = 0; c < 8; c++)
        acc += part[((size_t)(b * 8 + c)) * (2 * D_) + j];
    out[(size_t)b * (2 * D_) + j] = acc;
}

// ---------------- stylization ----------------
__global__ void styl_kernel(const float* __restrict__ y,
                            const float* __restrict__ g,
                            const float* __restrict__ bta,
                            const float* __restrict__ embout,
                            float* __restrict__ out) {
    int row = blockIdx.x;
    int b = row / T_;
    const float* yr = y + (size_t)row * D_;
    int tid = threadIdx.x;
    float v0 = yr[tid], v1 = yr[tid + 256];
    float s = v0 + v1, sq = v0*v0 + v1*v1;
    __shared__ float sh_s[8], sh_q[8];
    for (int o = 16; o > 0; o >>= 1) {
        s  += __shfl_xor_sync(0xffffffff, s,  o);
        sq += __shfl_xor_sync(0xffffffff, sq, o);
    }
    int warp = tid >> 5, lane = tid & 31;
    if (lane == 0) { sh_s[warp] = s; sh_q[warp] = sq; }
    __syncthreads();
    if (warp == 0) {
        s  = (lane < 8) ? sh_s[lane] : 0.f;
        sq = (lane < 8) ? sh_q[lane] : 0.f;
        for (int o = 4; o > 0; o >>= 1) {
            s  += __shfl_xor_sync(0xffffffff, s,  o);
            sq += __shfl_xor_sync(0xffffffff, sq, o);
        }
        if (lane == 0) { sh_s[0] = s; sh_q[0] = sq; }
    }
    __syncthreads();
    float mean = sh_s[0] * (1.f / D_);
    float var  = sh_q[0] * (1.f / D_) - mean * mean;
    float rs = rsqrtf(var + 1e-5f);
    const float* eo = embout + (size_t)b * (2 * D_);
    float* orow = out + (size_t)row * D_;
    {
        int c = tid;
        float ln = (v0 - mean) * rs * g[c] + bta[c];
        float hh = ln * (1.f + eo[c]) + eo[D_ + c];
        orow[c] = __fdividef(hh, 1.f + __expf(-hh));
    }
    {
        int c = tid + 256;
        float ln = (v1 - mean) * rs * g[c] + bta[c];
        float hh = ln * (1.f + eo[c]) + eo[D_ + c];
        orow[c] = __fdividef(hh, 1.f + __expf(-hh));
    }
}

// ---------------- launch ----------------
static cudaStream_t g_s2 = nullptr;
static cudaEvent_t g_ev_root = nullptr, g_ev_emb = nullptr,
                   g_ev_attn = nullptr, g_ev_tr = nullptr;

extern "C" void kernel_launch(void* const* d_in, const int* in_sizes, int n_in,
                              void* d_out, int out_size) {
    const float* x      = (const float*)d_in[0];
    const float* emb    = (const float*)d_in[1];
    const float* mask   = (const float*)d_in[2];
    const float* ln_g   = (const float*)d_in[3];
    const float* ln_b   = (const float*)d_in[4];
    const float* wq     = (const float*)d_in[5];
    const float* bq     = (const float*)d_in[6];
    const float* wk     = (const float*)d_in[7];
    const float* bk     = (const float*)d_in[8];
    const float* wv     = (const float*)d_in[9];
    const float* bv     = (const float*)d_in[10];
    const float* sb_g   = (const float*)d_in[11];
    const float* sb_b   = (const float*)d_in[12];
    const float* emb_w  = (const float*)d_in[13];
    const float* emb_b  = (const float*)d_in[14];
    const float* out_w  = (const float*)d_in[15];
    const float* out_b  = (const float*)d_in[16];

    float* out0 = (float*)d_out;                       // x + h : [4,1024,512]
    float* attn = out0 + (size_t)NTOK * D_;            // attention : [4,1024,1024,8]

    float *xn, *q, *k, *v, *y, *hb, *eo, *ep, *sb;
    cudaGetSymbolAddress((void**)&xn, g_xn);
    cudaGetSymbolAddress((void**)&q,  g_q);
    cudaGetSymbolAddress((void**)&k,  g_k);
    cudaGetSymbolAddress((void**)&v,  g_v);
    cudaGetSymbolAddress((void**)&y,  g_y);
    cudaGetSymbolAddress((void**)&hb, g_h);
    cudaGetSymbolAddress((void**)&eo, g_embout);
    cudaGetSymbolAddress((void**)&ep, g_embpart);
    cudaGetSymbolAddress((void**)&sb, g_sbuf);

    if (g_s2 == nullptr) {
        cudaStreamCreateWithFlags(&g_s2, cudaStreamNonBlocking);
        cudaEventCreateWithFlags(&g_ev_root, cudaEventDisableTiming);
        cudaEventCreateWithFlags(&g_ev_emb,  cudaEventDisableTiming);
        cudaEventCreateWithFlags(&g_ev_attn, cudaEventDisableTiming);
        cudaEventCreateWithFlags(&g_ev_tr,   cudaEventDisableTiming);
    }

    cudaFuncSetAttribute(attn_kernel, cudaFuncAttributeMaxDynamicSharedMemorySize,
                         ATTN_SMEM_BYTES);

    // fork: emb path on side stream
    cudaEventRecord(g_ev_root, 0);
    cudaStreamWaitEvent(g_s2, g_ev_root, 0);
    emb_partial<<<dim3(8, B_), 1024, 0, g_s2>>>(emb, emb_w, ep);
    emb_reduce<<<B_, 1024, 0, g_s2>>>(ep, emb_b, eo);
    cudaEventRecord(g_ev_emb, g_s2);

    // main: ln -> QKV -> attn
    ln_kernel<<<NTOK, 256>>>(x, ln_g, ln_b, xn);
    dim3 gq(D_ / 128, NTOK / 128, 3);
    sgemm_tf32_128<<<gq, 256>>>(xn, wq, wk, wv, bq, bk, bv, q, k, v,
                                nullptr, NTOK, D_, D_);
    attn_kernel<<<dim3(T_ / QROWS, H_, B_), ATHR, ATTN_SMEM_BYTES>>>(q, k, v, mask, sb, y);

    // fork: transpose on side stream
    cudaEventRecord(g_ev_attn, 0);
    cudaStreamWaitEvent(g_s2, g_ev_attn, 0);
    transpose_attn<<<dim3(T_ / 2, B_), 512, 0, g_s2>>>(sb, attn);
    cudaEventRecord(g_ev_tr, g_s2);

    // main: styl -> out GEMM (join emb first)
    cudaStreamWaitEvent(0, g_ev_emb, 0);
    styl_kernel<<<NTOK, 256>>>(y, sb_g, sb_b, eo, hb);
    dim3 go(D_ / 128, NTOK / 128, 1);
    sgemm_tf32_128<<<go, 256>>>(hb, out_w, out_w, out_w, out_b, out_b, out_b,
                                out0, out0, out0, x, NTOK, D_, D_);

    cudaStreamWaitEvent(0, g_ev_tr, 0);
}